// round 1
// baseline (speedup 1.0000x reference)
#include <cuda_runtime.h>
#include <math.h>

#define BB   96
#define NAA  48
#define FF   128
#define KK   64
#define LL   6
#define NN   (BB*NAA)          // 4608 nodes
#define F3   (3*FF)            // 384
#define CUTR 5.0f

// ---------------- device scratch (no allocations allowed) ----------------
__device__ float g_s   [NN*FF];        // scalar features
__device__ float g_v   [NN*F3];        // vector features [node][c][f]
__device__ float g_s2  [NN*FF];        // post-message s
__device__ float g_v2  [NN*F3];        // post-message v
__device__ float g_phi [NN*F3];        // message MLP output
__device__ float g_rbfc[NN*NAA*KK];    // env-premultiplied rbf per (node, slot)
__device__ float g_dirc[NN*NAA*3];     // unit direction per (node, slot)
__device__ float g_envc[NN*NAA];       // envelope per (node, slot)
__device__ int   g_nbr [NN*NAA];       // global sender index per (node, slot)
__device__ int   g_cnt [NN];           // neighbor count per node
__device__ float g_atom[NN];           // per-atom output

// ---------------- helpers ----------------
__device__ __forceinline__ float silu_f(float x) {
    return x / (1.0f + expf(-x));
}

__device__ __forceinline__ unsigned long long pk2(float lo, float hi) {
    unsigned long long r;
    asm("mov.b64 %0, {%1, %2};" : "=l"(r) : "f"(lo), "f"(hi));
    return r;
}
__device__ __forceinline__ unsigned long long ffma2(unsigned long long a,
                                                    unsigned long long b,
                                                    unsigned long long c) {
    unsigned long long d;
    asm("fma.rn.f32x2 %0, %1, %2, %3;" : "=l"(d) : "l"(a), "l"(b), "l"(c));
    return d;
}
__device__ __forceinline__ void upk2(unsigned long long a, float& lo, float& hi) {
    asm("mov.b64 {%0, %1}, %2;" : "=f"(lo), "=f"(hi) : "l"(a));
}

// ---------------- geometry precompute + neighbor compaction ----------------
__global__ void geom_kernel(const float* __restrict__ pos) {
    const int bi = blockIdx.x;                 // node index
    const int b  = bi / NAA;
    const int i  = bi % NAA;
    const int t  = threadIdx.x;                // 64 threads

    __shared__ float sd[NAA];
    __shared__ float sdir[NAA][3];
    __shared__ int   smask[NAA];
    __shared__ int   slots[NAA];
    __shared__ int   s_cnt;

    const float* pi = pos + (size_t)(b*NAA + i)*3;
    const float pix = pi[0], piy = pi[1], piz = pi[2];

    if (t < NAA) {
        const float* pj = pos + (size_t)(b*NAA + t)*3;
        float dx = pix - pj[0], dy = piy - pj[1], dz = piz - pj[2];
        float d2 = dx*dx + dy*dy + dz*dz;
        float d  = (t == i) ? 1.0f : sqrtf(d2);
        smask[t] = (t != i) && (d < CUTR);
        sd[t] = d;
        float inv = 1.0f / d;
        sdir[t][0] = dx*inv; sdir[t][1] = dy*inv; sdir[t][2] = dz*inv;
    }
    __syncthreads();
    if (t == 0) {
        int c = 0;
        for (int j = 0; j < NAA; j++) if (smask[j]) slots[c++] = j;
        s_cnt = c;
        g_cnt[bi] = c;
    }
    __syncthreads();
    const int cnt = s_cnt;

    const float GAMMA = (float)(1.0 / ((5.0/64.0)*(5.0/64.0) + 1e-9));
    const float STEP  = (float)(5.0 / 63.0);
    const float PI_F  = 3.14159265358979323846f;

    for (int s = 0; s < cnt; s++) {
        int j = slots[s];
        float d = sd[j];
        float env = 0.5f * (cosf(PI_F * d / CUTR) + 1.0f);
        float center = STEP * (float)t;
        float diff = d - center;
        g_rbfc[((size_t)bi*NAA + s)*KK + t] = env * expf(-GAMMA * diff * diff);
        if (t == 0) {
            g_envc[(size_t)bi*NAA + s] = env;
            g_nbr [(size_t)bi*NAA + s] = b*NAA + j;
            g_dirc[((size_t)bi*NAA + s)*3 + 0] = sdir[j][0];
            g_dirc[((size_t)bi*NAA + s)*3 + 1] = sdir[j][1];
            g_dirc[((size_t)bi*NAA + s)*3 + 2] = sdir[j][2];
        }
    }
}

// ---------------- init: s = emb[node_atom], v = 0 ----------------
__global__ void init_kernel(const float* __restrict__ emb,
                            const int*   __restrict__ node_atom) {
    const int bi = blockIdx.x;
    const int t  = threadIdx.x;                // 128
    const int a  = node_atom[bi];
    g_s[(size_t)bi*FF + t] = emb[(size_t)a*FF + t];
    g_v[(size_t)bi*F3 + t]          = 0.0f;
    g_v[(size_t)bi*F3 + FF + t]     = 0.0f;
    g_v[(size_t)bi*F3 + 2*FF + t]   = 0.0f;
}

// ---------------- phi = silu(s@w1+b1)@w2+b2 ----------------
__global__ void phi_kernel(const float* __restrict__ w1, const float* __restrict__ b1,
                           const float* __restrict__ w2, const float* __restrict__ b2) {
    const int bi = blockIdx.x;
    const int t  = threadIdx.x;                // 384
    __shared__ float ss[FF];
    __shared__ float sh[FF];
    if (t < FF) ss[t] = g_s[(size_t)bi*FF + t];
    __syncthreads();
    if (t < FF) {
        float acc = __ldg(&b1[t]);
        #pragma unroll 8
        for (int k = 0; k < FF; k++) acc = fmaf(ss[k], __ldg(&w1[k*FF + t]), acc);
        sh[t] = silu_f(acc);
    }
    __syncthreads();
    float acc = __ldg(&b2[t]);
    #pragma unroll 8
    for (int k = 0; k < FF; k++) acc = fmaf(sh[k], __ldg(&w2[k*F3 + t]), acc);
    g_phi[(size_t)bi*F3 + t] = acc;
}

// ---------------- message block: per target node, loop neighbors ----------------
__global__ __launch_bounds__(384, 1)
void msg_kernel(const float* __restrict__ rbf_w, const float* __restrict__ rbf_b) {
    const int bi = blockIdx.x;                 // target node (global)
    const int t  = threadIdx.x;                // 384
    const int chunk = t >> 7;                  // 0: ds, 1: dvv, 2: dvs
    const int f = t & 127;

    // W column (64 values for output feature t), pre-packed into f32x2 pairs
    unsigned long long Wp[KK/2];
    #pragma unroll
    for (int k = 0; k < KK/2; k++)
        Wp[k] = pk2(__ldg(&rbf_w[(2*k)*F3 + t]), __ldg(&rbf_w[(2*k+1)*F3 + t]));
    const float bias = __ldg(&rbf_b[t]);

    __shared__ __align__(16) unsigned long long sm_rbfp[KK/2];
    __shared__ float sm_dir[4];
    __shared__ float sm_env;
    __shared__ int   sm_j;
    __shared__ float sm_red[F3];

    float accA = 0.0f;                         // ds accumulator (chunk 0)
    float acc0 = 0.0f, acc1 = 0.0f, acc2 = 0.0f;  // dvv / dvs accumulators

    const int cnt = g_cnt[bi];
    for (int s = 0; s < cnt; s++) {
        __syncthreads();
        if (t < 16) {
            ((float4*)sm_rbfp)[t] =
                ((const float4*)(g_rbfc + ((size_t)bi*NAA + s)*KK))[t];
        } else if (t < 19) {
            sm_dir[t-16] = g_dirc[((size_t)bi*NAA + s)*3 + (t-16)];
        } else if (t == 19) {
            sm_env = g_envc[(size_t)bi*NAA + s];
        } else if (t == 20) {
            sm_j = g_nbr[(size_t)bi*NAA + s];
        }
        __syncthreads();

        // tval = env*bias + dot(env*rbf, Wcol)  — packed f32x2 FMA
        unsigned long long a2 = 0ull;
        #pragma unroll
        for (int k = 0; k < KK/2; k++) a2 = ffma2(sm_rbfp[k], Wp[k], a2);
        float lo, hi; upk2(a2, lo, hi);
        float tval = fmaf(sm_env, bias, lo + hi);

        const int jg = sm_j;
        float x = __ldg(&g_phi[(size_t)jg*F3 + t]) * tval;

        if (chunk == 0) {
            accA += x;
        } else if (chunk == 1) {
            const float* vj = g_v + (size_t)jg*F3 + f;
            acc0 = fmaf(x, __ldg(vj),         acc0);
            acc1 = fmaf(x, __ldg(vj + FF),    acc1);
            acc2 = fmaf(x, __ldg(vj + 2*FF),  acc2);
        } else {
            acc0 = fmaf(x, sm_dir[0], acc0);
            acc1 = fmaf(x, sm_dir[1], acc1);
            acc2 = fmaf(x, sm_dir[2], acc2);
        }
    }

    __syncthreads();
    if (chunk == 2) {
        sm_red[f]        = acc0;
        sm_red[FF + f]   = acc1;
        sm_red[2*FF + f] = acc2;
    }
    __syncthreads();
    if (chunk == 0) {
        g_s2[(size_t)bi*FF + f] = g_s[(size_t)bi*FF + f] + accA;
    } else if (chunk == 1) {
        size_t base = (size_t)bi*F3;
        g_v2[base + f]        = g_v[base + f]        + acc0 + sm_red[f];
        g_v2[base + FF + f]   = g_v[base + FF + f]   + acc1 + sm_red[FF + f];
        g_v2[base + 2*FF + f] = g_v[base + 2*FF + f] + acc2 + sm_red[2*FF + f];
    }
}

// ---------------- update block ----------------
__global__ void upd_kernel(const float* __restrict__ U,  const float* __restrict__ V,
                           const float* __restrict__ w1, const float* __restrict__ b1,
                           const float* __restrict__ w2, const float* __restrict__ b2) {
    const int bi = blockIdx.x;
    const int g  = threadIdx.x;                // 128
    __shared__ float sv[F3];
    __shared__ float scat[2*FF];
    __shared__ float sh[FF];

    size_t vb = (size_t)bi*F3;
    sv[g]        = g_v2[vb + g];
    sv[FF + g]   = g_v2[vb + FF + g];
    sv[2*FF + g] = g_v2[vb + 2*FF + g];
    const float s_in = g_s2[(size_t)bi*FF + g];
    scat[g] = s_in;
    __syncthreads();

    float Uv0=0.f,Uv1=0.f,Uv2=0.f,Vv0=0.f,Vv1=0.f,Vv2=0.f;
    #pragma unroll 4
    for (int k = 0; k < FF; k++) {
        float u  = __ldg(&U[k*FF + g]);
        float vw = __ldg(&V[k*FF + g]);
        float v0 = sv[k], v1 = sv[FF + k], v2 = sv[2*FF + k];
        Uv0 = fmaf(v0, u, Uv0);  Uv1 = fmaf(v1, u, Uv1);  Uv2 = fmaf(v2, u, Uv2);
        Vv0 = fmaf(v0, vw, Vv0); Vv1 = fmaf(v1, vw, Vv1); Vv2 = fmaf(v2, vw, Vv2);
    }
    scat[FF + g] = sqrtf(Vv0*Vv0 + Vv1*Vv1 + Vv2*Vv2 + 1e-8f);
    __syncthreads();

    float acc = __ldg(&b1[g]);
    #pragma unroll 8
    for (int k = 0; k < 2*FF; k++) acc = fmaf(scat[k], __ldg(&w1[k*FF + g]), acc);
    sh[g] = silu_f(acc);
    __syncthreads();

    float avv = __ldg(&b2[g]);
    float asv = __ldg(&b2[FF + g]);
    float ass = __ldg(&b2[2*FF + g]);
    #pragma unroll 4
    for (int k = 0; k < FF; k++) {
        float h = sh[k];
        avv = fmaf(h, __ldg(&w2[k*F3 + g]),        avv);
        asv = fmaf(h, __ldg(&w2[k*F3 + FF + g]),   asv);
        ass = fmaf(h, __ldg(&w2[k*F3 + 2*FF + g]), ass);
    }
    float dotUV = Uv0*Vv0 + Uv1*Vv1 + Uv2*Vv2;

    g_v[vb + g]        = sv[g]        + avv*Uv0;
    g_v[vb + FF + g]   = sv[FF + g]   + avv*Uv1;
    g_v[vb + 2*FF + g] = sv[2*FF + g] + avv*Uv2;
    g_s[(size_t)bi*FF + g] = s_in + asv*dotUV + ass;
}

// ---------------- output head ----------------
__global__ void out_atom_kernel(const float* __restrict__ w1, const float* __restrict__ b1,
                                const float* __restrict__ w2, const float* __restrict__ b2) {
    const int bi = blockIdx.x;
    const int t  = threadIdx.x;                // 128
    __shared__ float ss[FF];
    __shared__ float red[FF];
    ss[t] = g_s[(size_t)bi*FF + t];
    __syncthreads();
    float acc = __ldg(&b1[t]);
    #pragma unroll 8
    for (int k = 0; k < FF; k++) acc = fmaf(ss[k], __ldg(&w1[k*FF + t]), acc);
    float h = silu_f(acc);
    red[t] = h * __ldg(&w2[t]);
    __syncthreads();
    for (int ofs = 64; ofs > 0; ofs >>= 1) {
        if (t < ofs) red[t] += red[t + ofs];
        __syncthreads();
    }
    if (t == 0) g_atom[bi] = red[0] + __ldg(&b2[0]);
}

__global__ void out_reduce_kernel(float* __restrict__ out) {
    const int b = blockIdx.x;
    const int t = threadIdx.x;                 // 64
    __shared__ float r[64];
    r[t] = (t < NAA) ? g_atom[(size_t)b*NAA + t] : 0.0f;
    __syncthreads();
    for (int ofs = 32; ofs > 0; ofs >>= 1) {
        if (t < ofs) r[t] += r[t + ofs];
        __syncthreads();
    }
    if (t == 0) out[b] = r[0];
}

// ---------------- launch ----------------
extern "C" void kernel_launch(void* const* d_in, const int* in_sizes, int n_in,
                              void* d_out, int out_size) {
    const float* pos       = (const float*)d_in[1];
    const int*   node_atom = (const int*)  d_in[3];
    const float* emb       = (const float*)d_in[4];
    const float* msg_w1    = (const float*)d_in[5];
    const float* msg_b1    = (const float*)d_in[6];
    const float* msg_w2    = (const float*)d_in[7];
    const float* msg_b2    = (const float*)d_in[8];
    const float* rbf_w     = (const float*)d_in[9];
    const float* rbf_b     = (const float*)d_in[10];
    const float* upd_U     = (const float*)d_in[11];
    const float* upd_V     = (const float*)d_in[12];
    const float* upd_w1    = (const float*)d_in[13];
    const float* upd_b1    = (const float*)d_in[14];
    const float* upd_w2    = (const float*)d_in[15];
    const float* upd_b2    = (const float*)d_in[16];
    const float* out_w1    = (const float*)d_in[17];
    const float* out_b1    = (const float*)d_in[18];
    const float* out_w2    = (const float*)d_in[19];
    const float* out_b2    = (const float*)d_in[20];

    geom_kernel<<<NN, 64>>>(pos);
    init_kernel<<<NN, FF>>>(emb, node_atom);

    for (int l = 0; l < LL; l++) {
        phi_kernel<<<NN, F3>>>(msg_w1 + (size_t)l*FF*FF, msg_b1 + (size_t)l*FF,
                               msg_w2 + (size_t)l*FF*F3, msg_b2 + (size_t)l*F3);
        msg_kernel<<<NN, F3>>>(rbf_w + (size_t)l*KK*F3, rbf_b + (size_t)l*F3);
        upd_kernel<<<NN, FF>>>(upd_U + (size_t)l*FF*FF, upd_V + (size_t)l*FF*FF,
                               upd_w1 + (size_t)l*2*FF*FF, upd_b1 + (size_t)l*FF,
                               upd_w2 + (size_t)l*FF*F3,   upd_b2 + (size_t)l*F3);
    }

    out_atom_kernel<<<NN, FF>>>(out_w1, out_b1, out_w2, out_b2);
    out_reduce_kernel<<<BB, 64>>>((float*)d_out);
}

// round 4
// speedup vs baseline: 2.1120x; 2.1120x over previous
#include <cuda_runtime.h>
#include <math.h>

#define BB   96
#define NAA  48
#define FF   128
#define KK   64
#define LL   6
#define NN   (BB*NAA)          // 4608 nodes
#define F3   (3*FF)            // 384
#define CUTR 5.0f

#define NB_PHI 16
#define NB_MSG 8
#define NB_UPD 4

// ---------------- device scratch (no allocations allowed) ----------------
__device__ float g_s   [NN*FF];
__device__ float g_v   [NN*F3];
__device__ float g_s2  [NN*FF];
__device__ float g_v2  [NN*F3];
__device__ float g_phi [NN*F3];
__device__ __align__(16) float g_rbfc[NN*NAA*KK];   // env-premultiplied rbf
__device__ float g_dirc[NN*NAA*3];
__device__ float g_envc[NN*NAA];
__device__ int   g_nbr [NN*NAA];
__device__ int   g_cnt [NN];
__device__ float g_atom[NN];

// ---------------- helpers ----------------
__device__ __forceinline__ float silu_f(float x) {
    return x / (1.0f + expf(-x));
}
__device__ __forceinline__ unsigned long long pk2(float lo, float hi) {
    unsigned long long r;
    asm("mov.b64 %0, {%1, %2};" : "=l"(r) : "f"(lo), "f"(hi));
    return r;
}
__device__ __forceinline__ unsigned long long ffma2(unsigned long long a,
                                                    unsigned long long b,
                                                    unsigned long long c) {
    unsigned long long d;
    asm("fma.rn.f32x2 %0, %1, %2, %3;" : "=l"(d) : "l"(a), "l"(b), "l"(c));
    return d;
}
__device__ __forceinline__ void upk2(unsigned long long a, float& lo, float& hi) {
    asm("mov.b64 {%0, %1}, %2;" : "=f"(lo), "=f"(hi) : "l"(a));
}

// ---------------- geometry precompute + neighbor compaction ----------------
__global__ void geom_kernel(const float* __restrict__ pos) {
    const int bi = blockIdx.x;
    const int b  = bi / NAA;
    const int i  = bi % NAA;
    const int t  = threadIdx.x;                // 64 threads

    __shared__ float sd[NAA];
    __shared__ float sdir[NAA][3];
    __shared__ int   smask[NAA];
    __shared__ int   slots[NAA];
    __shared__ int   s_cnt;

    const float* pi = pos + (size_t)(b*NAA + i)*3;
    const float pix = pi[0], piy = pi[1], piz = pi[2];

    if (t < NAA) {
        const float* pj = pos + (size_t)(b*NAA + t)*3;
        float dx = pix - pj[0], dy = piy - pj[1], dz = piz - pj[2];
        float d2 = dx*dx + dy*dy + dz*dz;
        float d  = (t == i) ? 1.0f : sqrtf(d2);
        smask[t] = (t != i) && (d < CUTR);
        sd[t] = d;
        float inv = 1.0f / d;
        sdir[t][0] = dx*inv; sdir[t][1] = dy*inv; sdir[t][2] = dz*inv;
    }
    __syncthreads();
    if (t == 0) {
        int c = 0;
        for (int j = 0; j < NAA; j++) if (smask[j]) slots[c++] = j;
        s_cnt = c;
        g_cnt[bi] = c;
    }
    __syncthreads();
    const int cnt = s_cnt;

    const float GAMMA = (float)(1.0 / ((5.0/64.0)*(5.0/64.0) + 1e-9));
    const float STEP  = (float)(5.0 / 63.0);
    const float PI_F  = 3.14159265358979323846f;

    for (int s = 0; s < cnt; s++) {
        int j = slots[s];
        float d = sd[j];
        float env = 0.5f * (cosf(PI_F * d / CUTR) + 1.0f);
        float center = STEP * (float)t;
        float diff = d - center;
        g_rbfc[((size_t)bi*NAA + s)*KK + t] = env * expf(-GAMMA * diff * diff);
        if (t == 0) {
            g_envc[(size_t)bi*NAA + s] = env;
            g_nbr [(size_t)bi*NAA + s] = b*NAA + j;
            g_dirc[((size_t)bi*NAA + s)*3 + 0] = sdir[j][0];
            g_dirc[((size_t)bi*NAA + s)*3 + 1] = sdir[j][1];
            g_dirc[((size_t)bi*NAA + s)*3 + 2] = sdir[j][2];
        }
    }
}

// ---------------- init: s = emb[node_atom], v = 0 ----------------
__global__ void init_kernel(const float* __restrict__ emb,
                            const int*   __restrict__ node_atom) {
    const int bi = blockIdx.x;
    const int t  = threadIdx.x;                // 128
    const int a  = node_atom[bi];
    g_s[(size_t)bi*FF + t] = emb[(size_t)a*FF + t];
    g_v[(size_t)bi*F3 + t]          = 0.0f;
    g_v[(size_t)bi*F3 + FF + t]     = 0.0f;
    g_v[(size_t)bi*F3 + 2*FF + t]   = 0.0f;
}

// ---------------- phi (batched): silu(s@w1+b1)@w2+b2 for NB_PHI nodes ----------------
__global__ __launch_bounds__(384)
void phi_kernel_b(const float* __restrict__ w1, const float* __restrict__ b1,
                  const float* __restrict__ w2, const float* __restrict__ b2) {
    __shared__ float4 ss4[FF][NB_PHI/4];   // [k][node/4] transposed for broadcast LDS.128
    __shared__ float4 sh4[FF][NB_PHI/4];
    const int t = threadIdx.x;             // 384
    const int node0 = blockIdx.x * NB_PHI;

    for (int idx = t; idx < NB_PHI*FF; idx += 384) {
        int n = idx >> 7, k = idx & 127;
        ((float*)ss4[k])[n] = g_s[(size_t)(node0+n)*FF + k];
    }
    __syncthreads();

    if (t < FF) {
        float acc[NB_PHI];
        float bb = __ldg(&b1[t]);
        #pragma unroll
        for (int n = 0; n < NB_PHI; n++) acc[n] = bb;
        for (int k = 0; k < FF; k++) {
            float w = __ldg(&w1[k*FF + t]);
            #pragma unroll
            for (int n4 = 0; n4 < NB_PHI/4; n4++) {
                float4 s4 = ss4[k][n4];
                acc[4*n4+0] = fmaf(s4.x, w, acc[4*n4+0]);
                acc[4*n4+1] = fmaf(s4.y, w, acc[4*n4+1]);
                acc[4*n4+2] = fmaf(s4.z, w, acc[4*n4+2]);
                acc[4*n4+3] = fmaf(s4.w, w, acc[4*n4+3]);
            }
        }
        #pragma unroll
        for (int n = 0; n < NB_PHI; n++) ((float*)sh4[t])[n] = silu_f(acc[n]);
    }
    __syncthreads();

    {
        float acc[NB_PHI];
        float bb = __ldg(&b2[t]);
        #pragma unroll
        for (int n = 0; n < NB_PHI; n++) acc[n] = bb;
        for (int k = 0; k < FF; k++) {
            float w = __ldg(&w2[k*F3 + t]);
            #pragma unroll
            for (int n4 = 0; n4 < NB_PHI/4; n4++) {
                float4 h4 = sh4[k][n4];
                acc[4*n4+0] = fmaf(h4.x, w, acc[4*n4+0]);
                acc[4*n4+1] = fmaf(h4.y, w, acc[4*n4+1]);
                acc[4*n4+2] = fmaf(h4.z, w, acc[4*n4+2]);
                acc[4*n4+3] = fmaf(h4.w, w, acc[4*n4+3]);
            }
        }
        #pragma unroll
        for (int n = 0; n < NB_PHI; n++)
            g_phi[(size_t)(node0+n)*F3 + t] = acc[n];
    }
}

// ---------------- message block (batched, sync-free inner loop) ----------------
__global__ __launch_bounds__(384, 1)
void msg_kernel_b(const float* __restrict__ rbf_w, const float* __restrict__ rbf_b) {
    const int t = threadIdx.x;                 // 384
    const int chunk = t >> 7;                  // 0: ds, 1: dvv, 2: dvs
    const int f = t & 127;

    // W column for output feature t: 64 values packed as f32x2 pairs (loaded ONCE per block)
    unsigned long long Wp[KK/2];
    #pragma unroll
    for (int p = 0; p < KK/2; p++)
        Wp[p] = pk2(__ldg(&rbf_w[(2*p)*F3 + t]), __ldg(&rbf_w[(2*p+1)*F3 + t]));
    const float bias = __ldg(&rbf_b[t]);

    __shared__ __align__(16) float s_rbf[NAA*KK];   // 12KB
    __shared__ float s_dir[NAA*3];
    __shared__ float s_env[NAA];
    __shared__ int   s_nbr[NAA];
    __shared__ float s_red[F3];

    for (int n = 0; n < NB_MSG; n++) {
        const int bi = blockIdx.x * NB_MSG + n;
        const int cnt = g_cnt[bi];

        // ---- stage all edge data for this node (one sync) ----
        {
            const float4* src4 = (const float4*)(g_rbfc + (size_t)bi*NAA*KK);
            float4* dst4 = (float4*)s_rbf;
            for (int idx = t; idx < cnt*16; idx += 384) dst4[idx] = src4[idx];
            for (int idx = t; idx < cnt*3;  idx += 384) s_dir[idx] = g_dirc[(size_t)bi*NAA*3 + idx];
            for (int idx = t; idx < cnt;    idx += 384) {
                s_env[idx] = g_envc[(size_t)bi*NAA + idx];
                s_nbr[idx] = g_nbr [(size_t)bi*NAA + idx];
            }
        }
        __syncthreads();

        float accA = 0.0f, ac0 = 0.0f, ac1 = 0.0f, ac2 = 0.0f;

        for (int s = 0; s < cnt; s++) {
            const ulonglong2* rp = (const ulonglong2*)(s_rbf + s*KK);
            unsigned long long a0 = 0ull, a1 = 0ull, a2 = 0ull, a3 = 0ull;
            #pragma unroll
            for (int k2 = 0; k2 < 8; k2++) {
                ulonglong2 qa = rp[2*k2];
                ulonglong2 qb = rp[2*k2+1];
                a0 = ffma2(qa.x, Wp[4*k2+0], a0);
                a1 = ffma2(qa.y, Wp[4*k2+1], a1);
                a2 = ffma2(qb.x, Wp[4*k2+2], a2);
                a3 = ffma2(qb.y, Wp[4*k2+3], a3);
            }
            float l0,h0,l1,h1,l2,h2,l3,h3;
            upk2(a0,l0,h0); upk2(a1,l1,h1); upk2(a2,l2,h2); upk2(a3,l3,h3);
            float sum = ((l0+h0)+(l1+h1)) + ((l2+h2)+(l3+h3));
            float tval = fmaf(s_env[s], bias, sum);

            const int jg = s_nbr[s];
            float x = __ldg(&g_phi[(size_t)jg*F3 + t]) * tval;

            if (chunk == 0) {
                accA += x;
            } else if (chunk == 1) {
                const float* vj = g_v + (size_t)jg*F3 + f;
                ac0 = fmaf(x, __ldg(vj),        ac0);
                ac1 = fmaf(x, __ldg(vj + FF),   ac1);
                ac2 = fmaf(x, __ldg(vj + 2*FF), ac2);
            } else {
                ac0 = fmaf(x, s_dir[s*3+0], ac0);
                ac1 = fmaf(x, s_dir[s*3+1], ac1);
                ac2 = fmaf(x, s_dir[s*3+2], ac2);
            }
        }

        __syncthreads();
        if (chunk == 2) { s_red[f] = ac0; s_red[FF+f] = ac1; s_red[2*FF+f] = ac2; }
        __syncthreads();
        if (chunk == 0) {
            g_s2[(size_t)bi*FF + f] = g_s[(size_t)bi*FF + f] + accA;
        } else if (chunk == 1) {
            size_t base = (size_t)bi*F3;
            g_v2[base + f]        = g_v[base + f]        + ac0 + s_red[f];
            g_v2[base + FF + f]   = g_v[base + FF + f]   + ac1 + s_red[FF + f];
            g_v2[base + 2*FF + f] = g_v[base + 2*FF + f] + ac2 + s_red[2*FF + f];
        }
        __syncthreads();   // protect s_rbf / s_red before next node's staging
    }
}

// ---------------- update block (batched) ----------------
__global__ __launch_bounds__(384)
void upd_kernel_b(const float* __restrict__ U,  const float* __restrict__ V,
                  const float* __restrict__ w1, const float* __restrict__ b1,
                  const float* __restrict__ w2, const float* __restrict__ b2) {
    __shared__ float sv  [NB_UPD][3][FF];
    __shared__ float s_in[NB_UPD][FF];
    __shared__ float Uvs [NB_UPD][3][FF];
    __shared__ float Vvs [NB_UPD][3][FF];
    __shared__ float Vn  [NB_UPD][FF];
    __shared__ float hp  [3][NB_UPD][FF];
    __shared__ float4 hsh[FF];             // [k][4 nodes]
    __shared__ float ash [NB_UPD][F3];

    const int t = threadIdx.x;             // 384
    const int node0 = blockIdx.x * NB_UPD;
    const int g = t & 127;
    const int m = t >> 7;                  // 0..2

    for (int idx = t; idx < NB_UPD*F3; idx += 384)
        ((float*)sv)[idx] = g_v2[(size_t)node0*F3 + idx];
    for (int idx = t; idx < NB_UPD*FF; idx += 384)
        ((float*)s_in)[idx] = g_s2[(size_t)node0*FF + idx];
    __syncthreads();

    // Phase A: Uv, Vv   (thread t handles component m, feature g, all NB nodes)
    {
        float aU[NB_UPD] = {0,0,0,0}, aV[NB_UPD] = {0,0,0,0};
        for (int k = 0; k < FF; k++) {
            float u  = __ldg(&U[k*FF + g]);
            float vw = __ldg(&V[k*FF + g]);
            #pragma unroll
            for (int n = 0; n < NB_UPD; n++) {
                float sval = sv[n][m][k];
                aU[n] = fmaf(sval, u,  aU[n]);
                aV[n] = fmaf(sval, vw, aV[n]);
            }
        }
        #pragma unroll
        for (int n = 0; n < NB_UPD; n++) { Uvs[n][m][g] = aU[n]; Vvs[n][m][g] = aV[n]; }
    }
    __syncthreads();

    for (int idx = t; idx < NB_UPD*FF; idx += 384) {
        int n = idx >> 7, gg = idx & 127;
        float v0 = Vvs[n][0][gg], v1 = Vvs[n][1][gg], v2 = Vvs[n][2][gg];
        Vn[n][gg] = sqrtf(v0*v0 + v1*v1 + v2*v2 + 1e-8f);
    }
    __syncthreads();

    // Phase B: h = silu(cat(s,Vn) @ w1 + b1), k-range split across the 3 m-groups
    {
        int k0 = m*86, k1 = (m == 2) ? 256 : (k0 + 86);
        float acc[NB_UPD] = {0,0,0,0};
        for (int k = k0; k < k1; k++) {
            float w = __ldg(&w1[k*FF + g]);
            #pragma unroll
            for (int n = 0; n < NB_UPD; n++) {
                float c = (k < FF) ? s_in[n][k] : Vn[n][k-FF];
                acc[n] = fmaf(c, w, acc[n]);
            }
        }
        #pragma unroll
        for (int n = 0; n < NB_UPD; n++) hp[m][n][g] = acc[n];
    }
    __syncthreads();

    for (int idx = t; idx < NB_UPD*FF; idx += 384) {
        int n = idx >> 7, gg = idx & 127;
        float hs = hp[0][n][gg] + hp[1][n][gg] + hp[2][n][gg] + __ldg(&b1[gg]);
        ((float*)&hsh[gg])[n] = silu_f(hs);
    }
    __syncthreads();

    // Phase C: a = h @ w2 + b2   (thread t owns output column t for all NB nodes)
    {
        float acc[NB_UPD];
        float bb = __ldg(&b2[t]);
        #pragma unroll
        for (int n = 0; n < NB_UPD; n++) acc[n] = bb;
        for (int k = 0; k < FF; k++) {
            float w = __ldg(&w2[k*F3 + t]);
            float4 h4 = hsh[k];
            acc[0] = fmaf(h4.x, w, acc[0]);
            acc[1] = fmaf(h4.y, w, acc[1]);
            acc[2] = fmaf(h4.z, w, acc[2]);
            acc[3] = fmaf(h4.w, w, acc[3]);
        }
        #pragma unroll
        for (int n = 0; n < NB_UPD; n++) ash[n][t] = acc[n];
    }
    __syncthreads();

    // Final combine + writeback
    for (int idx = t; idx < NB_UPD*FF; idx += 384) {
        int n = idx >> 7, gg = idx & 127;
        float avv = ash[n][gg], asv = ash[n][FF+gg], ass = ash[n][2*FF+gg];
        float dot = Uvs[n][0][gg]*Vvs[n][0][gg] + Uvs[n][1][gg]*Vvs[n][1][gg]
                  + Uvs[n][2][gg]*Vvs[n][2][gg];
        size_t vb = (size_t)(node0+n)*F3;
        g_v[vb + gg]        = sv[n][0][gg] + avv*Uvs[n][0][gg];
        g_v[vb + FF + gg]   = sv[n][1][gg] + avv*Uvs[n][1][gg];
        g_v[vb + 2*FF + gg] = sv[n][2][gg] + avv*Uvs[n][2][gg];
        g_s[(size_t)(node0+n)*FF + gg] = s_in[n][gg] + asv*dot + ass;
    }
}

// ---------------- output head ----------------
__global__ void out_atom_kernel(const float* __restrict__ w1, const float* __restrict__ b1,
                                const float* __restrict__ w2, const float* __restrict__ b2) {
    const int bi = blockIdx.x;
    const int t  = threadIdx.x;                // 128
    __shared__ float ss[FF];
    __shared__ float red[FF];
    ss[t] = g_s[(size_t)bi*FF + t];
    __syncthreads();
    float acc = __ldg(&b1[t]);
    #pragma unroll 8
    for (int k = 0; k < FF; k++) acc = fmaf(ss[k], __ldg(&w1[k*FF + t]), acc);
    float h = silu_f(acc);
    red[t] = h * __ldg(&w2[t]);
    __syncthreads();
    for (int ofs = 64; ofs > 0; ofs >>= 1) {
        if (t < ofs) red[t] += red[t + ofs];
        __syncthreads();
    }
    if (t == 0) g_atom[bi] = red[0] + __ldg(&b2[0]);
}

__global__ void out_reduce_kernel(float* __restrict__ out) {
    const int b = blockIdx.x;
    const int t = threadIdx.x;                 // 64
    __shared__ float r[64];
    r[t] = (t < NAA) ? g_atom[(size_t)b*NAA + t] : 0.0f;
    __syncthreads();
    for (int ofs = 32; ofs > 0; ofs >>= 1) {
        if (t < ofs) r[t] += r[t + ofs];
        __syncthreads();
    }
    if (t == 0) out[b] = r[0];
}

// ---------------- launch ----------------
extern "C" void kernel_launch(void* const* d_in, const int* in_sizes, int n_in,
                              void* d_out, int out_size) {
    const float* pos       = (const float*)d_in[1];
    const int*   node_atom = (const int*)  d_in[3];
    const float* emb       = (const float*)d_in[4];
    const float* msg_w1    = (const float*)d_in[5];
    const float* msg_b1    = (const float*)d_in[6];
    const float* msg_w2    = (const float*)d_in[7];
    const float* msg_b2    = (const float*)d_in[8];
    const float* rbf_w     = (const float*)d_in[9];
    const float* rbf_b     = (const float*)d_in[10];
    const float* upd_U     = (const float*)d_in[11];
    const float* upd_V     = (const float*)d_in[12];
    const float* upd_w1    = (const float*)d_in[13];
    const float* upd_b1    = (const float*)d_in[14];
    const float* upd_w2    = (const float*)d_in[15];
    const float* upd_b2    = (const float*)d_in[16];
    const float* out_w1    = (const float*)d_in[17];
    const float* out_b1    = (const float*)d_in[18];
    const float* out_w2    = (const float*)d_in[19];
    const float* out_b2    = (const float*)d_in[20];

    geom_kernel<<<NN, 64>>>(pos);
    init_kernel<<<NN, FF>>>(emb, node_atom);

    for (int l = 0; l < LL; l++) {
        phi_kernel_b<<<NN/NB_PHI, 384>>>(msg_w1 + (size_t)l*FF*FF, msg_b1 + (size_t)l*FF,
                                         msg_w2 + (size_t)l*FF*F3, msg_b2 + (size_t)l*F3);
        msg_kernel_b<<<NN/NB_MSG, 384>>>(rbf_w + (size_t)l*KK*F3, rbf_b + (size_t)l*F3);
        upd_kernel_b<<<NN/NB_UPD, 384>>>(upd_U + (size_t)l*FF*FF, upd_V + (size_t)l*FF*FF,
                                         upd_w1 + (size_t)l*2*FF*FF, upd_b1 + (size_t)l*FF,
                                         upd_w2 + (size_t)l*FF*F3,   upd_b2 + (size_t)l*F3);
    }

    out_atom_kernel<<<NN, FF>>>(out_w1, out_b1, out_w2, out_b2);
    out_reduce_kernel<<<BB, 64>>>((float*)d_out);
}

// round 5
// speedup vs baseline: 2.4822x; 1.1753x over previous
#include <cuda_runtime.h>
#include <math.h>

#define BB   96
#define NAA  48
#define FF   128
#define KK   64
#define LL   6
#define NN   (BB*NAA)          // 4608 nodes
#define F3   (3*FF)            // 384
#define CUTR 5.0f

#define NB_PHI 16
#define NB_MSG 8               // 48 % 8 == 0 -> all targets of a block share one graph
#define NB_UPD 8

// msg dynamic smem layout (floats)
#define MS_PH   0                    // [48][384] phi of whole graph
#define MS_VV   (MS_PH + NAA*F3)     // [48][384] v of whole graph
#define MS_RBF  (MS_VV + NAA*F3)     // [48][64]
#define MS_DIR  (MS_RBF + NAA*KK)    // [48*3]
#define MS_ENV  (MS_DIR + NAA*3)     // [48]
#define MS_NBR  (MS_ENV + NAA)       // [48] (int)
#define MS_RED  (MS_NBR + NAA)       // [384]
#define MS_TOT  (MS_RED + F3)        // 40560 floats = 162240 B

// upd dynamic smem layout (floats)
#define US_SV   0                          // [8][3][128]
#define US_SIN  (US_SV  + NB_UPD*3*FF)     // [8][128]
#define US_UV   (US_SIN + NB_UPD*FF)       // [8][3][128]
#define US_VV   (US_UV  + NB_UPD*3*FF)     // [8][3][128]
#define US_VN   (US_VV  + NB_UPD*3*FF)     // [8][128]
#define US_HP   (US_VN  + NB_UPD*FF)       // [3][8][128]
#define US_HSH  (US_HP  + 3*NB_UPD*FF)     // [128][8]
#define US_ASH  (US_HSH + FF*NB_UPD)       // [8][384]
#define US_TOT  (US_ASH + NB_UPD*F3)       // 18432 floats = 73728 B

// ---------------- device scratch ----------------
__device__ float g_s   [NN*FF];
__device__ float g_v   [NN*F3];
__device__ float g_s2  [NN*FF];
__device__ float g_v2  [NN*F3];
__device__ float g_phi [NN*F3];
__device__ __align__(16) float g_rbfc[NN*NAA*KK];
__device__ float g_dirc[NN*NAA*3];
__device__ float g_envc[NN*NAA];
__device__ int   g_nbr [NN*NAA];
__device__ int   g_cnt [NN];
__device__ float g_atom[NN];

// ---------------- helpers ----------------
__device__ __forceinline__ float silu_f(float x) { return x / (1.0f + expf(-x)); }
__device__ __forceinline__ unsigned long long pk2(float lo, float hi) {
    unsigned long long r;
    asm("mov.b64 %0, {%1, %2};" : "=l"(r) : "f"(lo), "f"(hi));
    return r;
}
__device__ __forceinline__ unsigned long long ffma2(unsigned long long a,
                                                    unsigned long long b,
                                                    unsigned long long c) {
    unsigned long long d;
    asm("fma.rn.f32x2 %0, %1, %2, %3;" : "=l"(d) : "l"(a), "l"(b), "l"(c));
    return d;
}
__device__ __forceinline__ void upk2(unsigned long long a, float& lo, float& hi) {
    asm("mov.b64 {%0, %1}, %2;" : "=f"(lo), "=f"(hi) : "l"(a));
}

// ---------------- geometry precompute + neighbor compaction ----------------
__global__ void geom_kernel(const float* __restrict__ pos) {
    const int bi = blockIdx.x;
    const int b  = bi / NAA;
    const int i  = bi % NAA;
    const int t  = threadIdx.x;                // 64

    __shared__ float sd[NAA];
    __shared__ float sdir[NAA][3];
    __shared__ int   smask[NAA];
    __shared__ int   slots[NAA];
    __shared__ int   s_cnt;

    const float* pi = pos + (size_t)(b*NAA + i)*3;
    const float pix = pi[0], piy = pi[1], piz = pi[2];

    if (t < NAA) {
        const float* pj = pos + (size_t)(b*NAA + t)*3;
        float dx = pix - pj[0], dy = piy - pj[1], dz = piz - pj[2];
        float d2 = dx*dx + dy*dy + dz*dz;
        float d  = (t == i) ? 1.0f : sqrtf(d2);
        smask[t] = (t != i) && (d < CUTR);
        sd[t] = d;
        float inv = 1.0f / d;
        sdir[t][0] = dx*inv; sdir[t][1] = dy*inv; sdir[t][2] = dz*inv;
    }
    __syncthreads();
    if (t == 0) {
        int c = 0;
        for (int j = 0; j < NAA; j++) if (smask[j]) slots[c++] = j;
        s_cnt = c;
        g_cnt[bi] = c;
    }
    __syncthreads();
    const int cnt = s_cnt;

    const float GAMMA = (float)(1.0 / ((5.0/64.0)*(5.0/64.0) + 1e-9));
    const float STEP  = (float)(5.0 / 63.0);
    const float PI_F  = 3.14159265358979323846f;

    for (int s = 0; s < cnt; s++) {
        int j = slots[s];
        float d = sd[j];
        float env = 0.5f * (cosf(PI_F * d / CUTR) + 1.0f);
        float center = STEP * (float)t;
        float diff = d - center;
        g_rbfc[((size_t)bi*NAA + s)*KK + t] = env * expf(-GAMMA * diff * diff);
        if (t == 0) {
            g_envc[(size_t)bi*NAA + s] = env;
            g_nbr [(size_t)bi*NAA + s] = b*NAA + j;
            g_dirc[((size_t)bi*NAA + s)*3 + 0] = sdir[j][0];
            g_dirc[((size_t)bi*NAA + s)*3 + 1] = sdir[j][1];
            g_dirc[((size_t)bi*NAA + s)*3 + 2] = sdir[j][2];
        }
    }
}

// ---------------- init ----------------
__global__ void init_kernel(const float* __restrict__ emb,
                            const int*   __restrict__ node_atom) {
    const int bi = blockIdx.x;
    const int t  = threadIdx.x;                // 128
    const int a  = node_atom[bi];
    g_s[(size_t)bi*FF + t] = emb[(size_t)a*FF + t];
    g_v[(size_t)bi*F3 + t]          = 0.0f;
    g_v[(size_t)bi*F3 + FF + t]     = 0.0f;
    g_v[(size_t)bi*F3 + 2*FF + t]   = 0.0f;
}

// ---------------- phi (batched) ----------------
__global__ __launch_bounds__(384)
void phi_kernel_b(const float* __restrict__ w1, const float* __restrict__ b1,
                  const float* __restrict__ w2, const float* __restrict__ b2) {
    __shared__ float4 ss4[FF][NB_PHI/4];
    __shared__ float4 sh4[FF][NB_PHI/4];
    const int t = threadIdx.x;             // 384
    const int node0 = blockIdx.x * NB_PHI;

    for (int idx = t; idx < NB_PHI*FF; idx += 384) {
        int n = idx >> 7, k = idx & 127;
        ((float*)ss4[k])[n] = g_s[(size_t)(node0+n)*FF + k];
    }
    __syncthreads();

    if (t < FF) {
        float acc[NB_PHI];
        float bb = __ldg(&b1[t]);
        #pragma unroll
        for (int n = 0; n < NB_PHI; n++) acc[n] = bb;
        for (int k = 0; k < FF; k++) {
            float w = __ldg(&w1[k*FF + t]);
            #pragma unroll
            for (int n4 = 0; n4 < NB_PHI/4; n4++) {
                float4 s4 = ss4[k][n4];
                acc[4*n4+0] = fmaf(s4.x, w, acc[4*n4+0]);
                acc[4*n4+1] = fmaf(s4.y, w, acc[4*n4+1]);
                acc[4*n4+2] = fmaf(s4.z, w, acc[4*n4+2]);
                acc[4*n4+3] = fmaf(s4.w, w, acc[4*n4+3]);
            }
        }
        #pragma unroll
        for (int n = 0; n < NB_PHI; n++) ((float*)sh4[t])[n] = silu_f(acc[n]);
    }
    __syncthreads();

    {
        float acc[NB_PHI];
        float bb = __ldg(&b2[t]);
        #pragma unroll
        for (int n = 0; n < NB_PHI; n++) acc[n] = bb;
        for (int k = 0; k < FF; k++) {
            float w = __ldg(&w2[k*F3 + t]);
            #pragma unroll
            for (int n4 = 0; n4 < NB_PHI/4; n4++) {
                float4 h4 = sh4[k][n4];
                acc[4*n4+0] = fmaf(h4.x, w, acc[4*n4+0]);
                acc[4*n4+1] = fmaf(h4.y, w, acc[4*n4+1]);
                acc[4*n4+2] = fmaf(h4.z, w, acc[4*n4+2]);
                acc[4*n4+3] = fmaf(h4.w, w, acc[4*n4+3]);
            }
        }
        #pragma unroll
        for (int n = 0; n < NB_PHI; n++)
            g_phi[(size_t)(node0+n)*F3 + t] = acc[n];
    }
}

// ---------------- message block: whole-graph phi/v staged in SMEM ----------------
__global__ __launch_bounds__(384, 1)
void msg_kernel_g(const float* __restrict__ rbf_w, const float* __restrict__ rbf_b) {
    extern __shared__ float dsm[];
    float* s_ph  = dsm + MS_PH;
    float* s_vv  = dsm + MS_VV;
    float* s_rbf = dsm + MS_RBF;
    float* s_dir = dsm + MS_DIR;
    float* s_env = dsm + MS_ENV;
    int*   s_nbr = (int*)(dsm + MS_NBR);
    float* s_red = dsm + MS_RED;

    const int t = threadIdx.x;                 // 384
    const int chunk = t >> 7;                  // 0: ds, 1: dvv, 2: dvs
    const int f = t & 127;
    const int node0 = blockIdx.x * NB_MSG;
    const int gbase = (node0 / NAA) * NAA;     // first node of this graph

    // W column for feature t (loaded once per block)
    unsigned long long Wp[KK/2];
    #pragma unroll
    for (int p = 0; p < KK/2; p++)
        Wp[p] = pk2(__ldg(&rbf_w[(2*p)*F3 + t]), __ldg(&rbf_w[(2*p+1)*F3 + t]));
    const float bias = __ldg(&rbf_b[t]);

    // stage whole graph's phi and v (48*384 floats each)
    {
        const float4* sp = (const float4*)(g_phi + (size_t)gbase*F3);
        const float4* sv = (const float4*)(g_v   + (size_t)gbase*F3);
        float4* dp = (float4*)s_ph;
        float4* dv = (float4*)s_vv;
        #pragma unroll 2
        for (int idx = t; idx < NAA*F3/4; idx += 384) { dp[idx] = sp[idx]; dv[idx] = sv[idx]; }
    }
    __syncthreads();

    for (int n = 0; n < NB_MSG; n++) {
        const int bi = node0 + n;
        const int cnt = g_cnt[bi];

        // stage this target's edge data
        {
            const float4* src4 = (const float4*)(g_rbfc + (size_t)bi*NAA*KK);
            float4* dst4 = (float4*)s_rbf;
            for (int idx = t; idx < cnt*16; idx += 384) dst4[idx] = src4[idx];
            for (int idx = t; idx < cnt*3;  idx += 384) s_dir[idx] = g_dirc[(size_t)bi*NAA*3 + idx];
            for (int idx = t; idx < cnt;    idx += 384) {
                s_env[idx] = g_envc[(size_t)bi*NAA + idx];
                s_nbr[idx] = g_nbr [(size_t)bi*NAA + idx] - gbase;   // local sender
            }
        }
        __syncthreads();

        float accA = 0.0f, ac0 = 0.0f, ac1 = 0.0f, ac2 = 0.0f;

        for (int s = 0; s < cnt; s++) {
            const ulonglong2* rp = (const ulonglong2*)(s_rbf + s*KK);
            unsigned long long a0 = 0ull, a1 = 0ull, a2 = 0ull, a3 = 0ull;
            #pragma unroll
            for (int k2 = 0; k2 < 8; k2++) {
                ulonglong2 qa = rp[2*k2];
                ulonglong2 qb = rp[2*k2+1];
                a0 = ffma2(qa.x, Wp[4*k2+0], a0);
                a1 = ffma2(qa.y, Wp[4*k2+1], a1);
                a2 = ffma2(qb.x, Wp[4*k2+2], a2);
                a3 = ffma2(qb.y, Wp[4*k2+3], a3);
            }
            float l0,h0,l1,h1,l2,h2,l3,h3;
            upk2(a0,l0,h0); upk2(a1,l1,h1); upk2(a2,l2,h2); upk2(a3,l3,h3);
            float sum = ((l0+h0)+(l1+h1)) + ((l2+h2)+(l3+h3));
            float tval = fmaf(s_env[s], bias, sum);

            const int jl = s_nbr[s];
            float x = s_ph[jl*F3 + t] * tval;

            if (chunk == 0) {
                accA += x;
            } else if (chunk == 1) {
                const float* vj = s_vv + jl*F3 + f;
                ac0 = fmaf(x, vj[0],    ac0);
                ac1 = fmaf(x, vj[FF],   ac1);
                ac2 = fmaf(x, vj[2*FF], ac2);
            } else {
                ac0 = fmaf(x, s_dir[s*3+0], ac0);
                ac1 = fmaf(x, s_dir[s*3+1], ac1);
                ac2 = fmaf(x, s_dir[s*3+2], ac2);
            }
        }

        __syncthreads();
        if (chunk == 2) { s_red[f] = ac0; s_red[FF+f] = ac1; s_red[2*FF+f] = ac2; }
        __syncthreads();
        if (chunk == 0) {
            g_s2[(size_t)bi*FF + f] = g_s[(size_t)bi*FF + f] + accA;
        } else if (chunk == 1) {
            const float* vi = s_vv + (bi - gbase)*F3 + f;     // v_i from smem
            size_t base = (size_t)bi*F3;
            g_v2[base + f]        = vi[0]    + ac0 + s_red[f];
            g_v2[base + FF + f]   = vi[FF]   + ac1 + s_red[FF + f];
            g_v2[base + 2*FF + f] = vi[2*FF] + ac2 + s_red[2*FF + f];
        }
        __syncthreads();
    }
}

// ---------------- update block (batched x8, dynamic smem) ----------------
__global__ __launch_bounds__(384, 2)
void upd_kernel_b(const float* __restrict__ U,  const float* __restrict__ V,
                  const float* __restrict__ w1, const float* __restrict__ b1,
                  const float* __restrict__ w2, const float* __restrict__ b2) {
    extern __shared__ float usm[];
    float* sv   = usm + US_SV;     // [n][m][g]
    float* s_in = usm + US_SIN;    // [n][g]
    float* Uvs  = usm + US_UV;     // [n][m][g]
    float* Vvs  = usm + US_VV;     // [n][m][g]
    float* Vn   = usm + US_VN;     // [n][g]
    float* hp   = usm + US_HP;     // [m][n][g]
    float* hsh  = usm + US_HSH;    // [g][n]
    float* ash  = usm + US_ASH;    // [n][t]

    const int t = threadIdx.x;             // 384
    const int node0 = blockIdx.x * NB_UPD;
    const int g = t & 127;
    const int m = t >> 7;                  // 0..2

    for (int idx = t; idx < NB_UPD*F3; idx += 384)
        sv[idx] = g_v2[(size_t)node0*F3 + idx];
    for (int idx = t; idx < NB_UPD*FF; idx += 384)
        s_in[idx] = g_s2[(size_t)node0*FF + idx];
    __syncthreads();

    // Phase A: Uv, Vv
    {
        float aU[NB_UPD], aV[NB_UPD];
        #pragma unroll
        for (int n = 0; n < NB_UPD; n++) { aU[n] = 0.f; aV[n] = 0.f; }
        for (int k = 0; k < FF; k++) {
            float u  = __ldg(&U[k*FF + g]);
            float vw = __ldg(&V[k*FF + g]);
            #pragma unroll
            for (int n = 0; n < NB_UPD; n++) {
                float sval = sv[(n*3 + m)*FF + k];
                aU[n] = fmaf(sval, u,  aU[n]);
                aV[n] = fmaf(sval, vw, aV[n]);
            }
        }
        #pragma unroll
        for (int n = 0; n < NB_UPD; n++) {
            Uvs[(n*3 + m)*FF + g] = aU[n];
            Vvs[(n*3 + m)*FF + g] = aV[n];
        }
    }
    __syncthreads();

    for (int idx = t; idx < NB_UPD*FF; idx += 384) {
        int n = idx >> 7, gg = idx & 127;
        float v0 = Vvs[(n*3+0)*FF+gg], v1 = Vvs[(n*3+1)*FF+gg], v2 = Vvs[(n*3+2)*FF+gg];
        Vn[n*FF + gg] = sqrtf(v0*v0 + v1*v1 + v2*v2 + 1e-8f);
    }
    __syncthreads();

    // Phase B: h = silu(cat(s,Vn) @ w1 + b1), k-split across m-groups
    {
        int k0 = m*86, k1 = (m == 2) ? 256 : (k0 + 86);
        float acc[NB_UPD];
        #pragma unroll
        for (int n = 0; n < NB_UPD; n++) acc[n] = 0.f;
        for (int k = k0; k < k1; k++) {
            float w = __ldg(&w1[k*FF + g]);
            #pragma unroll
            for (int n = 0; n < NB_UPD; n++) {
                float c = (k < FF) ? s_in[n*FF + k] : Vn[n*FF + (k-FF)];
                acc[n] = fmaf(c, w, acc[n]);
            }
        }
        #pragma unroll
        for (int n = 0; n < NB_UPD; n++) hp[(m*NB_UPD + n)*FF + g] = acc[n];
    }
    __syncthreads();

    for (int idx = t; idx < NB_UPD*FF; idx += 384) {
        int n = idx >> 7, gg = idx & 127;
        float hs = hp[(0*NB_UPD+n)*FF+gg] + hp[(1*NB_UPD+n)*FF+gg] + hp[(2*NB_UPD+n)*FF+gg]
                 + __ldg(&b1[gg]);
        hsh[gg*NB_UPD + n] = silu_f(hs);
    }
    __syncthreads();

    // Phase C: a = h @ w2 + b2
    {
        float acc[NB_UPD];
        float bb = __ldg(&b2[t]);
        #pragma unroll
        for (int n = 0; n < NB_UPD; n++) acc[n] = bb;
        for (int k = 0; k < FF; k++) {
            float w = __ldg(&w2[k*F3 + t]);
            float4 h4a = ((const float4*)(hsh + k*NB_UPD))[0];
            float4 h4b = ((const float4*)(hsh + k*NB_UPD))[1];
            acc[0] = fmaf(h4a.x, w, acc[0]);
            acc[1] = fmaf(h4a.y, w, acc[1]);
            acc[2] = fmaf(h4a.z, w, acc[2]);
            acc[3] = fmaf(h4a.w, w, acc[3]);
            acc[4] = fmaf(h4b.x, w, acc[4]);
            acc[5] = fmaf(h4b.y, w, acc[5]);
            acc[6] = fmaf(h4b.z, w, acc[6]);
            acc[7] = fmaf(h4b.w, w, acc[7]);
        }
        #pragma unroll
        for (int n = 0; n < NB_UPD; n++) ash[n*F3 + t] = acc[n];
    }
    __syncthreads();

    // Final combine + writeback
    for (int idx = t; idx < NB_UPD*FF; idx += 384) {
        int n = idx >> 7, gg = idx & 127;
        float avv = ash[n*F3 + gg], asv = ash[n*F3 + FF+gg], ass = ash[n*F3 + 2*FF+gg];
        float u0 = Uvs[(n*3+0)*FF+gg], u1 = Uvs[(n*3+1)*FF+gg], u2 = Uvs[(n*3+2)*FF+gg];
        float w0 = Vvs[(n*3+0)*FF+gg], w1v = Vvs[(n*3+1)*FF+gg], w2v = Vvs[(n*3+2)*FF+gg];
        float dot = u0*w0 + u1*w1v + u2*w2v;
        size_t vb = (size_t)(node0+n)*F3;
        g_v[vb + gg]        = sv[(n*3+0)*FF+gg] + avv*u0;
        g_v[vb + FF + gg]   = sv[(n*3+1)*FF+gg] + avv*u1;
        g_v[vb + 2*FF + gg] = sv[(n*3+2)*FF+gg] + avv*u2;
        g_s[(size_t)(node0+n)*FF + gg] = s_in[n*FF + gg] + asv*dot + ass;
    }
}

// ---------------- output head ----------------
__global__ void out_atom_kernel(const float* __restrict__ w1, const float* __restrict__ b1,
                                const float* __restrict__ w2, const float* __restrict__ b2) {
    const int bi = blockIdx.x;
    const int t  = threadIdx.x;                // 128
    __shared__ float ss[FF];
    __shared__ float red[FF];
    ss[t] = g_s[(size_t)bi*FF + t];
    __syncthreads();
    float acc = __ldg(&b1[t]);
    #pragma unroll 8
    for (int k = 0; k < FF; k++) acc = fmaf(ss[k], __ldg(&w1[k*FF + t]), acc);
    float h = silu_f(acc);
    red[t] = h * __ldg(&w2[t]);
    __syncthreads();
    for (int ofs = 64; ofs > 0; ofs >>= 1) {
        if (t < ofs) red[t] += red[t + ofs];
        __syncthreads();
    }
    if (t == 0) g_atom[bi] = red[0] + __ldg(&b2[0]);
}

__global__ void out_reduce_kernel(float* __restrict__ out) {
    const int b = blockIdx.x;
    const int t = threadIdx.x;                 // 64
    __shared__ float r[64];
    r[t] = (t < NAA) ? g_atom[(size_t)b*NAA + t] : 0.0f;
    __syncthreads();
    for (int ofs = 32; ofs > 0; ofs >>= 1) {
        if (t < ofs) r[t] += r[t + ofs];
        __syncthreads();
    }
    if (t == 0) out[b] = r[0];
}

// ---------------- launch ----------------
extern "C" void kernel_launch(void* const* d_in, const int* in_sizes, int n_in,
                              void* d_out, int out_size) {
    const float* pos       = (const float*)d_in[1];
    const int*   node_atom = (const int*)  d_in[3];
    const float* emb       = (const float*)d_in[4];
    const float* msg_w1    = (const float*)d_in[5];
    const float* msg_b1    = (const float*)d_in[6];
    const float* msg_w2    = (const float*)d_in[7];
    const float* msg_b2    = (const float*)d_in[8];
    const float* rbf_w     = (const float*)d_in[9];
    const float* rbf_b     = (const float*)d_in[10];
    const float* upd_U     = (const float*)d_in[11];
    const float* upd_V     = (const float*)d_in[12];
    const float* upd_w1    = (const float*)d_in[13];
    const float* upd_b1    = (const float*)d_in[14];
    const float* upd_w2    = (const float*)d_in[15];
    const float* upd_b2    = (const float*)d_in[16];
    const float* out_w1    = (const float*)d_in[17];
    const float* out_b1    = (const float*)d_in[18];
    const float* out_w2    = (const float*)d_in[19];
    const float* out_b2    = (const float*)d_in[20];

    const int msg_smem = MS_TOT * sizeof(float);   // ~162 KB
    const int upd_smem = US_TOT * sizeof(float);   // ~73 KB
    cudaFuncSetAttribute(msg_kernel_g, cudaFuncAttributeMaxDynamicSharedMemorySize, msg_smem);
    cudaFuncSetAttribute(upd_kernel_b, cudaFuncAttributeMaxDynamicSharedMemorySize, upd_smem);

    geom_kernel<<<NN, 64>>>(pos);
    init_kernel<<<NN, FF>>>(emb, node_atom);

    for (int l = 0; l < LL; l++) {
        phi_kernel_b<<<NN/NB_PHI, 384>>>(msg_w1 + (size_t)l*FF*FF, msg_b1 + (size_t)l*FF,
                                         msg_w2 + (size_t)l*FF*F3, msg_b2 + (size_t)l*F3);
        msg_kernel_g<<<NN/NB_MSG, 384, msg_smem>>>(rbf_w + (size_t)l*KK*F3, rbf_b + (size_t)l*F3);
        upd_kernel_b<<<NN/NB_UPD, 384, upd_smem>>>(upd_U + (size_t)l*FF*FF, upd_V + (size_t)l*FF*FF,
                                                   upd_w1 + (size_t)l*2*FF*FF, upd_b1 + (size_t)l*FF,
                                                   upd_w2 + (size_t)l*FF*F3,   upd_b2 + (size_t)l*F3);
    }

    out_atom_kernel<<<NN, FF>>>(out_w1, out_b1, out_w2, out_b2);
    out_reduce_kernel<<<BB, 64>>>((float*)d_out);
}

// round 6
// speedup vs baseline: 2.6958x; 1.0861x over previous
#include <cuda_runtime.h>
#include <math.h>

#define BB   96
#define NAA  48
#define FF   128
#define KK   64
#define LL   6
#define NN   (BB*NAA)          // 4608 nodes
#define F3   (3*FF)            // 384
#define CUTR 5.0f

#define NB_PHI 16
#define NB_MSG 8               // 48 % 8 == 0 -> all targets of a block share one graph
#define NB_UPD 8

// upd dynamic smem layout (floats)
#define US_SV   0                          // [8][3][128]
#define US_SIN  (US_SV  + NB_UPD*3*FF)     // [8][128]
#define US_UV   (US_SIN + NB_UPD*FF)       // [8][3][128]
#define US_VV   (US_UV  + NB_UPD*3*FF)     // [8][3][128]
#define US_VN   (US_VV  + NB_UPD*3*FF)     // [8][128]
#define US_HP   (US_VN  + NB_UPD*FF)       // [3][8][128]
#define US_HSH  (US_HP  + 3*NB_UPD*FF)     // [128][8]
#define US_ASH  (US_HSH + FF*NB_UPD)       // [8][384]
#define US_TOT  (US_ASH + NB_UPD*F3)       // 18432 floats = 73728 B

// ---------------- device scratch ----------------
__device__ float g_s   [NN*FF];
__device__ float g_v   [NN*F3];
__device__ float g_s2  [NN*FF];
__device__ float g_v2  [NN*F3];        // dvv partial + v_i
__device__ float g_v2b [NN*F3];        // dvs partial
__device__ float g_phi [NN*F3];
__device__ __align__(16) float g_rbfc[NN*NAA*KK];
__device__ float g_dirc[NN*NAA*3];
__device__ float g_envc[NN*NAA];
__device__ int   g_nbr [NN*NAA];
__device__ int   g_cnt [NN];
__device__ float g_atom[NN];

// ---------------- helpers ----------------
__device__ __forceinline__ float silu_f(float x) { return x / (1.0f + expf(-x)); }
__device__ __forceinline__ unsigned long long pk2(float lo, float hi) {
    unsigned long long r;
    asm("mov.b64 %0, {%1, %2};" : "=l"(r) : "f"(lo), "f"(hi));
    return r;
}
__device__ __forceinline__ unsigned long long ffma2(unsigned long long a,
                                                    unsigned long long b,
                                                    unsigned long long c) {
    unsigned long long d;
    asm("fma.rn.f32x2 %0, %1, %2, %3;" : "=l"(d) : "l"(a), "l"(b), "l"(c));
    return d;
}
__device__ __forceinline__ void upk2(unsigned long long a, float& lo, float& hi) {
    asm("mov.b64 {%0, %1}, %2;" : "=f"(lo), "=f"(hi) : "l"(a));
}

// ---------------- geometry precompute + neighbor compaction ----------------
__global__ void geom_kernel(const float* __restrict__ pos) {
    const int bi = blockIdx.x;
    const int b  = bi / NAA;
    const int i  = bi % NAA;
    const int t  = threadIdx.x;                // 64

    __shared__ float sd[NAA];
    __shared__ float sdir[NAA][3];
    __shared__ int   smask[NAA];
    __shared__ int   slots[NAA];
    __shared__ int   s_cnt;

    const float* pi = pos + (size_t)(b*NAA + i)*3;
    const float pix = pi[0], piy = pi[1], piz = pi[2];

    if (t < NAA) {
        const float* pj = pos + (size_t)(b*NAA + t)*3;
        float dx = pix - pj[0], dy = piy - pj[1], dz = piz - pj[2];
        float d2 = dx*dx + dy*dy + dz*dz;
        float d  = (t == i) ? 1.0f : sqrtf(d2);
        smask[t] = (t != i) && (d < CUTR);
        sd[t] = d;
        float inv = 1.0f / d;
        sdir[t][0] = dx*inv; sdir[t][1] = dy*inv; sdir[t][2] = dz*inv;
    }
    __syncthreads();
    if (t == 0) {
        int c = 0;
        for (int j = 0; j < NAA; j++) if (smask[j]) slots[c++] = j;
        s_cnt = c;
        g_cnt[bi] = c;
    }
    __syncthreads();
    const int cnt = s_cnt;

    const float GAMMA = (float)(1.0 / ((5.0/64.0)*(5.0/64.0) + 1e-9));
    const float STEP  = (float)(5.0 / 63.0);
    const float PI_F  = 3.14159265358979323846f;

    for (int s = 0; s < cnt; s++) {
        int j = slots[s];
        float d = sd[j];
        float env = 0.5f * (cosf(PI_F * d / CUTR) + 1.0f);
        float center = STEP * (float)t;
        float diff = d - center;
        g_rbfc[((size_t)bi*NAA + s)*KK + t] = env * expf(-GAMMA * diff * diff);
        if (t == 0) {
            g_envc[(size_t)bi*NAA + s] = env;
            g_nbr [(size_t)bi*NAA + s] = b*NAA + j;
            g_dirc[((size_t)bi*NAA + s)*3 + 0] = sdir[j][0];
            g_dirc[((size_t)bi*NAA + s)*3 + 1] = sdir[j][1];
            g_dirc[((size_t)bi*NAA + s)*3 + 2] = sdir[j][2];
        }
    }
}

// ---------------- init ----------------
__global__ void init_kernel(const float* __restrict__ emb,
                            const int*   __restrict__ node_atom) {
    const int bi = blockIdx.x;
    const int t  = threadIdx.x;                // 128
    const int a  = node_atom[bi];
    g_s[(size_t)bi*FF + t] = emb[(size_t)a*FF + t];
    g_v[(size_t)bi*F3 + t]          = 0.0f;
    g_v[(size_t)bi*F3 + FF + t]     = 0.0f;
    g_v[(size_t)bi*F3 + 2*FF + t]   = 0.0f;
}

// ---------------- phi (batched) ----------------
__global__ __launch_bounds__(384)
void phi_kernel_b(const float* __restrict__ w1, const float* __restrict__ b1,
                  const float* __restrict__ w2, const float* __restrict__ b2) {
    __shared__ float4 ss4[FF][NB_PHI/4];
    __shared__ float4 sh4[FF][NB_PHI/4];
    const int t = threadIdx.x;             // 384
    const int node0 = blockIdx.x * NB_PHI;

    for (int idx = t; idx < NB_PHI*FF; idx += 384) {
        int n = idx >> 7, k = idx & 127;
        ((float*)ss4[k])[n] = g_s[(size_t)(node0+n)*FF + k];
    }
    __syncthreads();

    if (t < FF) {
        float acc[NB_PHI];
        float bb = __ldg(&b1[t]);
        #pragma unroll
        for (int n = 0; n < NB_PHI; n++) acc[n] = bb;
        for (int k = 0; k < FF; k++) {
            float w = __ldg(&w1[k*FF + t]);
            #pragma unroll
            for (int n4 = 0; n4 < NB_PHI/4; n4++) {
                float4 s4 = ss4[k][n4];
                acc[4*n4+0] = fmaf(s4.x, w, acc[4*n4+0]);
                acc[4*n4+1] = fmaf(s4.y, w, acc[4*n4+1]);
                acc[4*n4+2] = fmaf(s4.z, w, acc[4*n4+2]);
                acc[4*n4+3] = fmaf(s4.w, w, acc[4*n4+3]);
            }
        }
        #pragma unroll
        for (int n = 0; n < NB_PHI; n++) ((float*)sh4[t])[n] = silu_f(acc[n]);
    }
    __syncthreads();

    {
        float acc[NB_PHI];
        float bb = __ldg(&b2[t]);
        #pragma unroll
        for (int n = 0; n < NB_PHI; n++) acc[n] = bb;
        for (int k = 0; k < FF; k++) {
            float w = __ldg(&w2[k*F3 + t]);
            #pragma unroll
            for (int n4 = 0; n4 < NB_PHI/4; n4++) {
                float4 h4 = sh4[k][n4];
                acc[4*n4+0] = fmaf(h4.x, w, acc[4*n4+0]);
                acc[4*n4+1] = fmaf(h4.y, w, acc[4*n4+1]);
                acc[4*n4+2] = fmaf(h4.z, w, acc[4*n4+2]);
                acc[4*n4+3] = fmaf(h4.w, w, acc[4*n4+3]);
            }
        }
        #pragma unroll
        for (int n = 0; n < NB_PHI; n++)
            g_phi[(size_t)(node0+n)*F3 + t] = acc[n];
    }
}

// ---------------- message block: chunk-split 128-thread blocks ----------------
// blockIdx.x: node group (NB_MSG nodes, same graph); blockIdx.y = chunk (0 ds, 1 dvv, 2 dvs)
__global__ __launch_bounds__(128, 4)
void msg_kernel_c(const float* __restrict__ rbf_w, const float* __restrict__ rbf_b) {
    __shared__ __align__(16) float s_rbf[NAA*KK];   // 12.3 KB
    __shared__ float s_phi[NAA*FF];                 // 24.6 KB (phi slice for this chunk)
    __shared__ float s_dir[NAA*3];
    __shared__ float s_env[NAA];
    __shared__ int   s_nbr[NAA];

    const int f = threadIdx.x;                 // 128
    const int chunk = blockIdx.y;              // 0..2
    const int t = chunk*FF + f;                // global feature column
    const int node0 = blockIdx.x * NB_MSG;
    const int gbase = (node0 / NAA) * NAA;

    // W column for feature t (64 values, packed f32x2), loaded once per block
    unsigned long long Wp[KK/2];
    #pragma unroll
    for (int p = 0; p < KK/2; p++)
        Wp[p] = pk2(__ldg(&rbf_w[(2*p)*F3 + t]), __ldg(&rbf_w[(2*p+1)*F3 + t]));
    const float bias = __ldg(&rbf_b[t]);

    // stage the whole graph's phi slice for this chunk: [48][128]
    for (int idx = f; idx < NAA*FF; idx += 128) {
        int j = idx >> 7, ff = idx & 127;
        s_phi[idx] = g_phi[(size_t)(gbase + j)*F3 + chunk*FF + ff];
    }
    __syncthreads();

    for (int n = 0; n < NB_MSG; n++) {
        const int bi = node0 + n;
        const int cnt = g_cnt[bi];

        // stage this target's edge data
        {
            const float4* src4 = (const float4*)(g_rbfc + (size_t)bi*NAA*KK);
            float4* dst4 = (float4*)s_rbf;
            for (int idx = f; idx < cnt*16; idx += 128) dst4[idx] = src4[idx];
            if (chunk == 2)
                for (int idx = f; idx < cnt*3; idx += 128)
                    s_dir[idx] = g_dirc[(size_t)bi*NAA*3 + idx];
            for (int idx = f; idx < cnt; idx += 128) {
                s_env[idx] = g_envc[(size_t)bi*NAA + idx];
                s_nbr[idx] = g_nbr [(size_t)bi*NAA + idx] - gbase;
            }
        }
        __syncthreads();

        float ac0 = 0.0f, ac1 = 0.0f, ac2 = 0.0f;

        for (int s = 0; s < cnt; s++) {
            const ulonglong2* rp = (const ulonglong2*)(s_rbf + s*KK);
            unsigned long long a0 = 0ull, a1 = 0ull, a2 = 0ull, a3 = 0ull;
            #pragma unroll
            for (int k2 = 0; k2 < 8; k2++) {
                ulonglong2 qa = rp[2*k2];
                ulonglong2 qb = rp[2*k2+1];
                a0 = ffma2(qa.x, Wp[4*k2+0], a0);
                a1 = ffma2(qa.y, Wp[4*k2+1], a1);
                a2 = ffma2(qb.x, Wp[4*k2+2], a2);
                a3 = ffma2(qb.y, Wp[4*k2+3], a3);
            }
            float l0,h0,l1,h1,l2,h2,l3,h3;
            upk2(a0,l0,h0); upk2(a1,l1,h1); upk2(a2,l2,h2); upk2(a3,l3,h3);
            float sum = ((l0+h0)+(l1+h1)) + ((l2+h2)+(l3+h3));
            float tval = fmaf(s_env[s], bias, sum);

            const int jl = s_nbr[s];
            float x = s_phi[jl*FF + f] * tval;

            if (chunk == 0) {
                ac0 += x;
            } else if (chunk == 1) {
                const float* vj = g_v + (size_t)(gbase + jl)*F3 + f;
                ac0 = fmaf(x, __ldg(vj),        ac0);
                ac1 = fmaf(x, __ldg(vj + FF),   ac1);
                ac2 = fmaf(x, __ldg(vj + 2*FF), ac2);
            } else {
                ac0 = fmaf(x, s_dir[s*3+0], ac0);
                ac1 = fmaf(x, s_dir[s*3+1], ac1);
                ac2 = fmaf(x, s_dir[s*3+2], ac2);
            }
        }

        if (chunk == 0) {
            g_s2[(size_t)bi*FF + f] = __ldg(&g_s[(size_t)bi*FF + f]) + ac0;
        } else if (chunk == 1) {
            size_t base = (size_t)bi*F3;
            g_v2[base + f]        = __ldg(&g_v[base + f])        + ac0;
            g_v2[base + FF + f]   = __ldg(&g_v[base + FF + f])   + ac1;
            g_v2[base + 2*FF + f] = __ldg(&g_v[base + 2*FF + f]) + ac2;
        } else {
            size_t base = (size_t)bi*F3;
            g_v2b[base + f]        = ac0;
            g_v2b[base + FF + f]   = ac1;
            g_v2b[base + 2*FF + f] = ac2;
        }
        __syncthreads();   // protect s_rbf before next node's staging
    }
}

// ---------------- update block (batched x8, dynamic smem) ----------------
__global__ __launch_bounds__(384, 2)
void upd_kernel_b(const float* __restrict__ U,  const float* __restrict__ V,
                  const float* __restrict__ w1, const float* __restrict__ b1,
                  const float* __restrict__ w2, const float* __restrict__ b2) {
    extern __shared__ float usm[];
    float* sv   = usm + US_SV;
    float* s_in = usm + US_SIN;
    float* Uvs  = usm + US_UV;
    float* Vvs  = usm + US_VV;
    float* Vn   = usm + US_VN;
    float* hp   = usm + US_HP;
    float* hsh  = usm + US_HSH;
    float* ash  = usm + US_ASH;

    const int t = threadIdx.x;             // 384
    const int node0 = blockIdx.x * NB_UPD;
    const int g = t & 127;
    const int m = t >> 7;                  // 0..2

    for (int idx = t; idx < NB_UPD*F3; idx += 384)
        sv[idx] = g_v2[(size_t)node0*F3 + idx] + g_v2b[(size_t)node0*F3 + idx];
    for (int idx = t; idx < NB_UPD*FF; idx += 384)
        s_in[idx] = g_s2[(size_t)node0*FF + idx];
    __syncthreads();

    // Phase A: Uv, Vv
    {
        float aU[NB_UPD], aV[NB_UPD];
        #pragma unroll
        for (int n = 0; n < NB_UPD; n++) { aU[n] = 0.f; aV[n] = 0.f; }
        for (int k = 0; k < FF; k++) {
            float u  = __ldg(&U[k*FF + g]);
            float vw = __ldg(&V[k*FF + g]);
            #pragma unroll
            for (int n = 0; n < NB_UPD; n++) {
                float sval = sv[(n*3 + m)*FF + k];
                aU[n] = fmaf(sval, u,  aU[n]);
                aV[n] = fmaf(sval, vw, aV[n]);
            }
        }
        #pragma unroll
        for (int n = 0; n < NB_UPD; n++) {
            Uvs[(n*3 + m)*FF + g] = aU[n];
            Vvs[(n*3 + m)*FF + g] = aV[n];
        }
    }
    __syncthreads();

    for (int idx = t; idx < NB_UPD*FF; idx += 384) {
        int n = idx >> 7, gg = idx & 127;
        float v0 = Vvs[(n*3+0)*FF+gg], v1 = Vvs[(n*3+1)*FF+gg], v2 = Vvs[(n*3+2)*FF+gg];
        Vn[n*FF + gg] = sqrtf(v0*v0 + v1*v1 + v2*v2 + 1e-8f);
    }
    __syncthreads();

    // Phase B: h = silu(cat(s,Vn) @ w1 + b1), k-split across m-groups
    {
        int k0 = m*86, k1 = (m == 2) ? 256 : (k0 + 86);
        float acc[NB_UPD];
        #pragma unroll
        for (int n = 0; n < NB_UPD; n++) acc[n] = 0.f;
        for (int k = k0; k < k1; k++) {
            float w = __ldg(&w1[k*FF + g]);
            #pragma unroll
            for (int n = 0; n < NB_UPD; n++) {
                float c = (k < FF) ? s_in[n*FF + k] : Vn[n*FF + (k-FF)];
                acc[n] = fmaf(c, w, acc[n]);
            }
        }
        #pragma unroll
        for (int n = 0; n < NB_UPD; n++) hp[(m*NB_UPD + n)*FF + g] = acc[n];
    }
    __syncthreads();

    for (int idx = t; idx < NB_UPD*FF; idx += 384) {
        int n = idx >> 7, gg = idx & 127;
        float hs = hp[(0*NB_UPD+n)*FF+gg] + hp[(1*NB_UPD+n)*FF+gg] + hp[(2*NB_UPD+n)*FF+gg]
                 + __ldg(&b1[gg]);
        hsh[gg*NB_UPD + n] = silu_f(hs);
    }
    __syncthreads();

    // Phase C: a = h @ w2 + b2
    {
        float acc[NB_UPD];
        float bb = __ldg(&b2[t]);
        #pragma unroll
        for (int n = 0; n < NB_UPD; n++) acc[n] = bb;
        for (int k = 0; k < FF; k++) {
            float w = __ldg(&w2[k*F3 + t]);
            float4 h4a = ((const float4*)(hsh + k*NB_UPD))[0];
            float4 h4b = ((const float4*)(hsh + k*NB_UPD))[1];
            acc[0] = fmaf(h4a.x, w, acc[0]);
            acc[1] = fmaf(h4a.y, w, acc[1]);
            acc[2] = fmaf(h4a.z, w, acc[2]);
            acc[3] = fmaf(h4a.w, w, acc[3]);
            acc[4] = fmaf(h4b.x, w, acc[4]);
            acc[5] = fmaf(h4b.y, w, acc[5]);
            acc[6] = fmaf(h4b.z, w, acc[6]);
            acc[7] = fmaf(h4b.w, w, acc[7]);
        }
        #pragma unroll
        for (int n = 0; n < NB_UPD; n++) ash[n*F3 + t] = acc[n];
    }
    __syncthreads();

    // Final combine + writeback
    for (int idx = t; idx < NB_UPD*FF; idx += 384) {
        int n = idx >> 7, gg = idx & 127;
        float avv = ash[n*F3 + gg], asv = ash[n*F3 + FF+gg], ass = ash[n*F3 + 2*FF+gg];
        float u0 = Uvs[(n*3+0)*FF+gg], u1 = Uvs[(n*3+1)*FF+gg], u2 = Uvs[(n*3+2)*FF+gg];
        float w0 = Vvs[(n*3+0)*FF+gg], w1v = Vvs[(n*3+1)*FF+gg], w2v = Vvs[(n*3+2)*FF+gg];
        float dot = u0*w0 + u1*w1v + u2*w2v;
        size_t vb = (size_t)(node0+n)*F3;
        g_v[vb + gg]        = sv[(n*3+0)*FF+gg] + avv*u0;
        g_v[vb + FF + gg]   = sv[(n*3+1)*FF+gg] + avv*u1;
        g_v[vb + 2*FF + gg] = sv[(n*3+2)*FF+gg] + avv*u2;
        g_s[(size_t)(node0+n)*FF + gg] = s_in[n*FF + gg] + asv*dot + ass;
    }
}

// ---------------- output head ----------------
__global__ void out_atom_kernel(const float* __restrict__ w1, const float* __restrict__ b1,
                                const float* __restrict__ w2, const float* __restrict__ b2) {
    const int bi = blockIdx.x;
    const int t  = threadIdx.x;                // 128
    __shared__ float ss[FF];
    __shared__ float red[FF];
    ss[t] = g_s[(size_t)bi*FF + t];
    __syncthreads();
    float acc = __ldg(&b1[t]);
    #pragma unroll 8
    for (int k = 0; k < FF; k++) acc = fmaf(ss[k], __ldg(&w1[k*FF + t]), acc);
    float h = silu_f(acc);
    red[t] = h * __ldg(&w2[t]);
    __syncthreads();
    for (int ofs = 64; ofs > 0; ofs >>= 1) {
        if (t < ofs) red[t] += red[t + ofs];
        __syncthreads();
    }
    if (t == 0) g_atom[bi] = red[0] + __ldg(&b2[0]);
}

__global__ void out_reduce_kernel(float* __restrict__ out) {
    const int b = blockIdx.x;
    const int t = threadIdx.x;                 // 64
    __shared__ float r[64];
    r[t] = (t < NAA) ? g_atom[(size_t)b*NAA + t] : 0.0f;
    __syncthreads();
    for (int ofs = 32; ofs > 0; ofs >>= 1) {
        if (t < ofs) r[t] += r[t + ofs];
        __syncthreads();
    }
    if (t == 0) out[b] = r[0];
}

// ---------------- launch ----------------
extern "C" void kernel_launch(void* const* d_in, const int* in_sizes, int n_in,
                              void* d_out, int out_size) {
    const float* pos       = (const float*)d_in[1];
    const int*   node_atom = (const int*)  d_in[3];
    const float* emb       = (const float*)d_in[4];
    const float* msg_w1    = (const float*)d_in[5];
    const float* msg_b1    = (const float*)d_in[6];
    const float* msg_w2    = (const float*)d_in[7];
    const float* msg_b2    = (const float*)d_in[8];
    const float* rbf_w     = (const float*)d_in[9];
    const float* rbf_b     = (const float*)d_in[10];
    const float* upd_U     = (const float*)d_in[11];
    const float* upd_V     = (const float*)d_in[12];
    const float* upd_w1    = (const float*)d_in[13];
    const float* upd_b1    = (const float*)d_in[14];
    const float* upd_w2    = (const float*)d_in[15];
    const float* upd_b2    = (const float*)d_in[16];
    const float* out_w1    = (const float*)d_in[17];
    const float* out_b1    = (const float*)d_in[18];
    const float* out_w2    = (const float*)d_in[19];
    const float* out_b2    = (const float*)d_in[20];

    const int upd_smem = US_TOT * sizeof(float);   // ~73 KB
    cudaFuncSetAttribute(upd_kernel_b, cudaFuncAttributeMaxDynamicSharedMemorySize, upd_smem);

    geom_kernel<<<NN, 64>>>(pos);
    init_kernel<<<NN, FF>>>(emb, node_atom);

    dim3 msg_grid(NN/NB_MSG, 3);
    for (int l = 0; l < LL; l++) {
        phi_kernel_b<<<NN/NB_PHI, 384>>>(msg_w1 + (size_t)l*FF*FF, msg_b1 + (size_t)l*FF,
                                         msg_w2 + (size_t)l*FF*F3, msg_b2 + (size_t)l*F3);
        msg_kernel_c<<<msg_grid, 128>>>(rbf_w + (size_t)l*KK*F3, rbf_b + (size_t)l*F3);
        upd_kernel_b<<<NN/NB_UPD, 384, upd_smem>>>(upd_U + (size_t)l*FF*FF, upd_V + (size_t)l*FF*FF,
                                                   upd_w1 + (size_t)l*2*FF*FF, upd_b1 + (size_t)l*FF,
                                                   upd_w2 + (size_t)l*FF*F3,   upd_b2 + (size_t)l*F3);
    }

    out_atom_kernel<<<NN, FF>>>(out_w1, out_b1, out_w2, out_b2);
    out_reduce_kernel<<<BB, 64>>>((float*)d_out);
}

// round 7
// speedup vs baseline: 3.0607x; 1.1354x over previous
#include <cuda_runtime.h>
#include <math.h>

#define BB   96
#define NAA  48
#define FF   128
#define KK   64
#define LL   6
#define NN   (BB*NAA)          // 4608 nodes
#define F3   (3*FF)            // 384
#define CUTR 5.0f

#define NB_PHI 16
#define NB_MSG 8
#define NB_UPD 8

// upd dynamic smem layout (floats)
#define US_SV   0                          // [8][3][128]   original layout (for writeback)
#define US_SIN  (US_SV  + NB_UPD*3*FF)     // [8][128]
#define US_UV   (US_SIN + NB_UPD*FF)       // [8][3][128]
#define US_VV   (US_UV  + NB_UPD*3*FF)     // [8][3][128]
#define US_VN   (US_VV  + NB_UPD*3*FF)     // [8][128]
#define US_HP   (US_VN  + NB_UPD*FF)       // [3][8][128]
#define US_HSH  (US_HP  + 3*NB_UPD*FF)     // [128][8]   n-fastest
#define US_ASH  (US_HSH + FF*NB_UPD)       // [8][384]
#define US_SVT  (US_ASH + NB_UPD*F3)       // [384][8]   transposed v (n-fastest)
#define US_CAT  (US_SVT + F3*NB_UPD)       // [256][8]   cat(s,Vn) transposed
#define US_TOT  (US_CAT + 2*FF*NB_UPD)     // 23552 floats = 94208 B

// ---------------- device scratch ----------------
__device__ float g_s   [NN*FF];
__device__ float g_v   [NN*F3];
__device__ float g_s2  [NN*FF];
__device__ float g_v2  [NN*F3];
__device__ float g_v2b [NN*F3];
__device__ float g_phi [NN*F3];
__device__ __align__(16) float g_rbfc[NN*NAA*KK];
__device__ float g_dirc[NN*NAA*3];
__device__ float g_envc[NN*NAA];
__device__ int   g_nbr [NN*NAA];
__device__ int   g_cnt [NN];
__device__ float g_atom[NN];

// ---------------- helpers ----------------
typedef unsigned long long ull;
__device__ __forceinline__ float silu_f(float x) { return x / (1.0f + expf(-x)); }
__device__ __forceinline__ ull pk2(float lo, float hi) {
    ull r; asm("mov.b64 %0, {%1, %2};" : "=l"(r) : "f"(lo), "f"(hi)); return r;
}
__device__ __forceinline__ ull ffma2(ull a, ull b, ull c) {
    ull d; asm("fma.rn.f32x2 %0, %1, %2, %3;" : "=l"(d) : "l"(a), "l"(b), "l"(c)); return d;
}
__device__ __forceinline__ ull add2(ull a, ull b) {
    ull d; asm("add.rn.f32x2 %0, %1, %2;" : "=l"(d) : "l"(a), "l"(b)); return d;
}
__device__ __forceinline__ void upk2(ull a, float& lo, float& hi) {
    asm("mov.b64 {%0, %1}, %2;" : "=f"(lo), "=f"(hi) : "l"(a));
}

// ---------------- geometry precompute + neighbor compaction ----------------
__global__ void geom_kernel(const float* __restrict__ pos) {
    const int bi = blockIdx.x;
    const int b  = bi / NAA;
    const int i  = bi % NAA;
    const int t  = threadIdx.x;                // 64

    __shared__ float sd[NAA];
    __shared__ float sdir[NAA][3];
    __shared__ int   smask[NAA];
    __shared__ int   slots[NAA];
    __shared__ int   s_cnt;

    const float* pi = pos + (size_t)(b*NAA + i)*3;
    const float pix = pi[0], piy = pi[1], piz = pi[2];

    if (t < NAA) {
        const float* pj = pos + (size_t)(b*NAA + t)*3;
        float dx = pix - pj[0], dy = piy - pj[1], dz = piz - pj[2];
        float d2 = dx*dx + dy*dy + dz*dz;
        float d  = (t == i) ? 1.0f : sqrtf(d2);
        smask[t] = (t != i) && (d < CUTR);
        sd[t] = d;
        float inv = 1.0f / d;
        sdir[t][0] = dx*inv; sdir[t][1] = dy*inv; sdir[t][2] = dz*inv;
    }
    __syncthreads();
    if (t == 0) {
        int c = 0;
        for (int j = 0; j < NAA; j++) if (smask[j]) slots[c++] = j;
        s_cnt = c;
        g_cnt[bi] = c;
    }
    __syncthreads();
    const int cnt = s_cnt;

    const float GAMMA = (float)(1.0 / ((5.0/64.0)*(5.0/64.0) + 1e-9));
    const float STEP  = (float)(5.0 / 63.0);
    const float PI_F  = 3.14159265358979323846f;

    for (int s = 0; s < cnt; s++) {
        int j = slots[s];
        float d = sd[j];
        float env = 0.5f * (cosf(PI_F * d / CUTR) + 1.0f);
        float center = STEP * (float)t;
        float diff = d - center;
        g_rbfc[((size_t)bi*NAA + s)*KK + t] = env * expf(-GAMMA * diff * diff);
        if (t == 0) {
            g_envc[(size_t)bi*NAA + s] = env;
            g_nbr [(size_t)bi*NAA + s] = b*NAA + j;
            g_dirc[((size_t)bi*NAA + s)*3 + 0] = sdir[j][0];
            g_dirc[((size_t)bi*NAA + s)*3 + 1] = sdir[j][1];
            g_dirc[((size_t)bi*NAA + s)*3 + 2] = sdir[j][2];
        }
    }
}

// ---------------- init ----------------
__global__ void init_kernel(const float* __restrict__ emb,
                            const int*   __restrict__ node_atom) {
    const int bi = blockIdx.x;
    const int t  = threadIdx.x;                // 128
    const int a  = node_atom[bi];
    g_s[(size_t)bi*FF + t] = emb[(size_t)a*FF + t];
    g_v[(size_t)bi*F3 + t]          = 0.0f;
    g_v[(size_t)bi*F3 + FF + t]     = 0.0f;
    g_v[(size_t)bi*F3 + 2*FF + t]   = 0.0f;
}

// ---------------- phi (batched, f32x2 node-pairs) ----------------
__global__ __launch_bounds__(384)
void phi_kernel_b(const float* __restrict__ w1, const float* __restrict__ b1,
                  const float* __restrict__ w2, const float* __restrict__ b2) {
    __shared__ __align__(16) float ss[FF][NB_PHI];   // k-major, node-fastest
    __shared__ __align__(16) float sh[FF][NB_PHI];
    const int t = threadIdx.x;             // 384
    const int node0 = blockIdx.x * NB_PHI;

    for (int idx = t; idx < NB_PHI*FF; idx += 384) {
        int n = idx >> 7, k = idx & 127;
        ss[k][n] = g_s[(size_t)(node0+n)*FF + k];
    }
    __syncthreads();

    if (t < FF) {
        ull acc2[NB_PHI/2];
        float bb = __ldg(&b1[t]);
        ull bb2 = pk2(bb, bb);
        #pragma unroll
        for (int i = 0; i < NB_PHI/2; i++) acc2[i] = bb2;
        for (int k = 0; k < FF; k++) {
            float w = __ldg(&w1[k*FF + t]);
            ull w2p = pk2(w, w);
            const ulonglong2* sp = (const ulonglong2*)&ss[k][0];
            ulonglong2 q0 = sp[0], q1 = sp[1], q2 = sp[2], q3 = sp[3];
            acc2[0] = ffma2(q0.x, w2p, acc2[0]);
            acc2[1] = ffma2(q0.y, w2p, acc2[1]);
            acc2[2] = ffma2(q1.x, w2p, acc2[2]);
            acc2[3] = ffma2(q1.y, w2p, acc2[3]);
            acc2[4] = ffma2(q2.x, w2p, acc2[4]);
            acc2[5] = ffma2(q2.y, w2p, acc2[5]);
            acc2[6] = ffma2(q3.x, w2p, acc2[6]);
            acc2[7] = ffma2(q3.y, w2p, acc2[7]);
        }
        #pragma unroll
        for (int i = 0; i < NB_PHI/2; i++) {
            float lo, hi; upk2(acc2[i], lo, hi);
            sh[t][2*i]   = silu_f(lo);
            sh[t][2*i+1] = silu_f(hi);
        }
    }
    __syncthreads();

    {
        ull acc2[NB_PHI/2];
        float bb = __ldg(&b2[t]);
        ull bb2 = pk2(bb, bb);
        #pragma unroll
        for (int i = 0; i < NB_PHI/2; i++) acc2[i] = bb2;
        for (int k = 0; k < FF; k++) {
            float w = __ldg(&w2[k*F3 + t]);
            ull w2p = pk2(w, w);
            const ulonglong2* sp = (const ulonglong2*)&sh[k][0];
            ulonglong2 q0 = sp[0], q1 = sp[1], q2 = sp[2], q3 = sp[3];
            acc2[0] = ffma2(q0.x, w2p, acc2[0]);
            acc2[1] = ffma2(q0.y, w2p, acc2[1]);
            acc2[2] = ffma2(q1.x, w2p, acc2[2]);
            acc2[3] = ffma2(q1.y, w2p, acc2[3]);
            acc2[4] = ffma2(q2.x, w2p, acc2[4]);
            acc2[5] = ffma2(q2.y, w2p, acc2[5]);
            acc2[6] = ffma2(q3.x, w2p, acc2[6]);
            acc2[7] = ffma2(q3.y, w2p, acc2[7]);
        }
        #pragma unroll
        for (int i = 0; i < NB_PHI/2; i++) {
            float lo, hi; upk2(acc2[i], lo, hi);
            g_phi[(size_t)(node0+2*i)*F3   + t] = lo;
            g_phi[(size_t)(node0+2*i+1)*F3 + t] = hi;
        }
    }
}

// ---------------- message block: chunk-split, 2-edge unrolled ----------------
__global__ __launch_bounds__(128, 4)
void msg_kernel_c(const float* __restrict__ rbf_w, const float* __restrict__ rbf_b) {
    __shared__ __align__(16) float s_rbf[NAA*KK];   // 12.3 KB
    __shared__ float s_phi[NAA*FF];                 // 24.6 KB
    __shared__ float s_dir[NAA*3];
    __shared__ float s_env[NAA];
    __shared__ int   s_nbr[NAA];

    const int f = threadIdx.x;                 // 128
    const int chunk = blockIdx.y;              // 0..2
    const int t = chunk*FF + f;
    const int node0 = blockIdx.x * NB_MSG;
    const int gbase = (node0 / NAA) * NAA;

    ull Wp[KK/2];
    #pragma unroll
    for (int p = 0; p < KK/2; p++)
        Wp[p] = pk2(__ldg(&rbf_w[(2*p)*F3 + t]), __ldg(&rbf_w[(2*p+1)*F3 + t]));
    const float bias = __ldg(&rbf_b[t]);

    for (int idx = f; idx < NAA*FF; idx += 128) {
        int j = idx >> 7, ff = idx & 127;
        s_phi[idx] = g_phi[(size_t)(gbase + j)*F3 + chunk*FF + ff];
    }
    __syncthreads();

    for (int n = 0; n < NB_MSG; n++) {
        const int bi = node0 + n;
        const int cnt = g_cnt[bi];

        {
            const float4* src4 = (const float4*)(g_rbfc + (size_t)bi*NAA*KK);
            float4* dst4 = (float4*)s_rbf;
            for (int idx = f; idx < cnt*16; idx += 128) dst4[idx] = src4[idx];
            if (chunk == 2)
                for (int idx = f; idx < cnt*3; idx += 128)
                    s_dir[idx] = g_dirc[(size_t)bi*NAA*3 + idx];
            for (int idx = f; idx < cnt; idx += 128) {
                s_env[idx] = g_envc[(size_t)bi*NAA + idx];
                s_nbr[idx] = g_nbr [(size_t)bi*NAA + idx] - gbase;
            }
        }
        __syncthreads();

        float ac0 = 0.0f, ac1 = 0.0f, ac2 = 0.0f;

        int s = 0;
        for (; s + 2 <= cnt; s += 2) {
            const ulonglong2* rpA = (const ulonglong2*)(s_rbf + s*KK);
            const ulonglong2* rpB = rpA + 16;
            ull a0=0,a1=0,a2=0,a3=0,b0=0,b1=0,b2=0,b3=0;
            #pragma unroll
            for (int k2 = 0; k2 < 8; k2++) {
                ulonglong2 qa = rpA[2*k2], qa2 = rpA[2*k2+1];
                ulonglong2 qb = rpB[2*k2], qb2 = rpB[2*k2+1];
                a0 = ffma2(qa.x,  Wp[4*k2+0], a0);
                a1 = ffma2(qa.y,  Wp[4*k2+1], a1);
                a2 = ffma2(qa2.x, Wp[4*k2+2], a2);
                a3 = ffma2(qa2.y, Wp[4*k2+3], a3);
                b0 = ffma2(qb.x,  Wp[4*k2+0], b0);
                b1 = ffma2(qb.y,  Wp[4*k2+1], b1);
                b2 = ffma2(qb2.x, Wp[4*k2+2], b2);
                b3 = ffma2(qb2.y, Wp[4*k2+3], b3);
            }
            ull sa = add2(add2(a0,a1), add2(a2,a3));
            ull sb = add2(add2(b0,b1), add2(b2,b3));
            float la, ha, lb, hb;
            upk2(sa, la, ha); upk2(sb, lb, hb);
            float tvalA = fmaf(s_env[s],   bias, la + ha);
            float tvalB = fmaf(s_env[s+1], bias, lb + hb);

            const int jA = s_nbr[s], jB = s_nbr[s+1];
            float xA = s_phi[jA*FF + f] * tvalA;
            float xB = s_phi[jB*FF + f] * tvalB;

            if (chunk == 0) {
                ac0 += xA + xB;
            } else if (chunk == 1) {
                const float* vjA = g_v + (size_t)(gbase + jA)*F3 + f;
                const float* vjB = g_v + (size_t)(gbase + jB)*F3 + f;
                float vA0 = __ldg(vjA), vA1 = __ldg(vjA+FF), vA2 = __ldg(vjA+2*FF);
                float vB0 = __ldg(vjB), vB1 = __ldg(vjB+FF), vB2 = __ldg(vjB+2*FF);
                ac0 = fmaf(xA, vA0, ac0); ac1 = fmaf(xA, vA1, ac1); ac2 = fmaf(xA, vA2, ac2);
                ac0 = fmaf(xB, vB0, ac0); ac1 = fmaf(xB, vB1, ac1); ac2 = fmaf(xB, vB2, ac2);
            } else {
                ac0 = fmaf(xA, s_dir[s*3+0], ac0);
                ac1 = fmaf(xA, s_dir[s*3+1], ac1);
                ac2 = fmaf(xA, s_dir[s*3+2], ac2);
                ac0 = fmaf(xB, s_dir[s*3+3], ac0);
                ac1 = fmaf(xB, s_dir[s*3+4], ac1);
                ac2 = fmaf(xB, s_dir[s*3+5], ac2);
            }
        }
        if (s < cnt) {
            const ulonglong2* rp = (const ulonglong2*)(s_rbf + s*KK);
            ull a0=0,a1=0,a2=0,a3=0;
            #pragma unroll
            for (int k2 = 0; k2 < 8; k2++) {
                ulonglong2 qa = rp[2*k2], qa2 = rp[2*k2+1];
                a0 = ffma2(qa.x,  Wp[4*k2+0], a0);
                a1 = ffma2(qa.y,  Wp[4*k2+1], a1);
                a2 = ffma2(qa2.x, Wp[4*k2+2], a2);
                a3 = ffma2(qa2.y, Wp[4*k2+3], a3);
            }
            ull sa = add2(add2(a0,a1), add2(a2,a3));
            float la, ha; upk2(sa, la, ha);
            float tval = fmaf(s_env[s], bias, la + ha);
            const int jl = s_nbr[s];
            float x = s_phi[jl*FF + f] * tval;
            if (chunk == 0) {
                ac0 += x;
            } else if (chunk == 1) {
                const float* vj = g_v + (size_t)(gbase + jl)*F3 + f;
                ac0 = fmaf(x, __ldg(vj),        ac0);
                ac1 = fmaf(x, __ldg(vj + FF),   ac1);
                ac2 = fmaf(x, __ldg(vj + 2*FF), ac2);
            } else {
                ac0 = fmaf(x, s_dir[s*3+0], ac0);
                ac1 = fmaf(x, s_dir[s*3+1], ac1);
                ac2 = fmaf(x, s_dir[s*3+2], ac2);
            }
        }

        if (chunk == 0) {
            g_s2[(size_t)bi*FF + f] = __ldg(&g_s[(size_t)bi*FF + f]) + ac0;
        } else if (chunk == 1) {
            size_t base = (size_t)bi*F3;
            g_v2[base + f]        = __ldg(&g_v[base + f])        + ac0;
            g_v2[base + FF + f]   = __ldg(&g_v[base + FF + f])   + ac1;
            g_v2[base + 2*FF + f] = __ldg(&g_v[base + 2*FF + f]) + ac2;
        } else {
            size_t base = (size_t)bi*F3;
            g_v2b[base + f]        = ac0;
            g_v2b[base + FF + f]   = ac1;
            g_v2b[base + 2*FF + f] = ac2;
        }
        __syncthreads();
    }
}

// ---------------- update block (batched x8, f32x2 node-pairs) ----------------
__global__ __launch_bounds__(384, 2)
void upd_kernel_b(const float* __restrict__ U,  const float* __restrict__ V,
                  const float* __restrict__ w1, const float* __restrict__ b1,
                  const float* __restrict__ w2, const float* __restrict__ b2) {
    extern __shared__ float usm[];
    float* sv   = usm + US_SV;
    float* s_in = usm + US_SIN;
    float* Uvs  = usm + US_UV;
    float* Vvs  = usm + US_VV;
    float* Vn   = usm + US_VN;
    float* hp   = usm + US_HP;
    float* hsh  = usm + US_HSH;
    float* ash  = usm + US_ASH;
    float* sv_t = usm + US_SVT;
    float* cat_t= usm + US_CAT;

    const int t = threadIdx.x;             // 384
    const int node0 = blockIdx.x * NB_UPD;
    const int g = t & 127;
    const int m = t >> 7;                  // 0..2

    for (int idx = t; idx < NB_UPD*F3; idx += 384) {
        float val = g_v2[(size_t)node0*F3 + idx] + g_v2b[(size_t)node0*F3 + idx];
        sv[idx] = val;
        int n = idx / F3, r = idx - n*F3;
        sv_t[r*NB_UPD + n] = val;
    }
    for (int idx = t; idx < NB_UPD*FF; idx += 384)
        s_in[idx] = g_s2[(size_t)node0*FF + idx];
    __syncthreads();

    // Phase A: Uv, Vv  (packed node-pairs)
    {
        ull aU2[NB_UPD/2] = {0,0,0,0}, aV2[NB_UPD/2] = {0,0,0,0};
        for (int k = 0; k < FF; k++) {
            float u  = __ldg(&U[k*FF + g]);
            float vw = __ldg(&V[k*FF + g]);
            ull u2  = pk2(u, u);
            ull vw2 = pk2(vw, vw);
            const ulonglong2* sp = (const ulonglong2*)(sv_t + (m*FF + k)*NB_UPD);
            ulonglong2 q0 = sp[0], q1 = sp[1];
            aU2[0] = ffma2(q0.x, u2,  aU2[0]);
            aU2[1] = ffma2(q0.y, u2,  aU2[1]);
            aU2[2] = ffma2(q1.x, u2,  aU2[2]);
            aU2[3] = ffma2(q1.y, u2,  aU2[3]);
            aV2[0] = ffma2(q0.x, vw2, aV2[0]);
            aV2[1] = ffma2(q0.y, vw2, aV2[1]);
            aV2[2] = ffma2(q1.x, vw2, aV2[2]);
            aV2[3] = ffma2(q1.y, vw2, aV2[3]);
        }
        #pragma unroll
        for (int i = 0; i < NB_UPD/2; i++) {
            float lo, hi;
            upk2(aU2[i], lo, hi);
            Uvs[((2*i)*3 + m)*FF + g]   = lo;
            Uvs[((2*i+1)*3 + m)*FF + g] = hi;
            upk2(aV2[i], lo, hi);
            Vvs[((2*i)*3 + m)*FF + g]   = lo;
            Vvs[((2*i+1)*3 + m)*FF + g] = hi;
        }
    }
    __syncthreads();

    for (int idx = t; idx < NB_UPD*FF; idx += 384) {
        int n = idx >> 7, gg = idx & 127;
        float v0 = Vvs[(n*3+0)*FF+gg], v1 = Vvs[(n*3+1)*FF+gg], v2 = Vvs[(n*3+2)*FF+gg];
        Vn[n*FF + gg] = sqrtf(v0*v0 + v1*v1 + v2*v2 + 1e-8f);
    }
    __syncthreads();

    // build transposed concat input [k 0..255][n]
    for (int idx = t; idx < NB_UPD*2*FF; idx += 384) {
        int n = idx >> 8, k = idx & 255;
        float c = (k < FF) ? s_in[n*FF + k] : Vn[n*FF + (k-FF)];
        cat_t[k*NB_UPD + n] = c;
    }
    __syncthreads();

    // Phase B: h partial (k-split across m-groups), packed node-pairs
    {
        int k0 = m*86, k1 = (m == 2) ? 256 : (k0 + 86);
        ull acc2[NB_UPD/2] = {0,0,0,0};
        for (int k = k0; k < k1; k++) {
            float w = __ldg(&w1[k*FF + g]);
            ull w2p = pk2(w, w);
            const ulonglong2* sp = (const ulonglong2*)(cat_t + k*NB_UPD);
            ulonglong2 q0 = sp[0], q1 = sp[1];
            acc2[0] = ffma2(q0.x, w2p, acc2[0]);
            acc2[1] = ffma2(q0.y, w2p, acc2[1]);
            acc2[2] = ffma2(q1.x, w2p, acc2[2]);
            acc2[3] = ffma2(q1.y, w2p, acc2[3]);
        }
        #pragma unroll
        for (int i = 0; i < NB_UPD/2; i++) {
            float lo, hi; upk2(acc2[i], lo, hi);
            hp[(m*NB_UPD + 2*i)*FF + g]   = lo;
            hp[(m*NB_UPD + 2*i+1)*FF + g] = hi;
        }
    }
    __syncthreads();

    for (int idx = t; idx < NB_UPD*FF; idx += 384) {
        int n = idx >> 7, gg = idx & 127;
        float hs = hp[(0*NB_UPD+n)*FF+gg] + hp[(1*NB_UPD+n)*FF+gg] + hp[(2*NB_UPD+n)*FF+gg]
                 + __ldg(&b1[gg]);
        hsh[gg*NB_UPD + n] = silu_f(hs);
    }
    __syncthreads();

    // Phase C: a = h @ w2 + b2, packed node-pairs
    {
        ull acc2[NB_UPD/2];
        float bb = __ldg(&b2[t]);
        ull bb2 = pk2(bb, bb);
        #pragma unroll
        for (int i = 0; i < NB_UPD/2; i++) acc2[i] = bb2;
        for (int k = 0; k < FF; k++) {
            float w = __ldg(&w2[k*F3 + t]);
            ull w2p = pk2(w, w);
            const ulonglong2* sp = (const ulonglong2*)(hsh + k*NB_UPD);
            ulonglong2 q0 = sp[0], q1 = sp[1];
            acc2[0] = ffma2(q0.x, w2p, acc2[0]);
            acc2[1] = ffma2(q0.y, w2p, acc2[1]);
            acc2[2] = ffma2(q1.x, w2p, acc2[2]);
            acc2[3] = ffma2(q1.y, w2p, acc2[3]);
        }
        #pragma unroll
        for (int i = 0; i < NB_UPD/2; i++) {
            float lo, hi; upk2(acc2[i], lo, hi);
            ash[(2*i)*F3 + t]   = lo;
            ash[(2*i+1)*F3 + t] = hi;
        }
    }
    __syncthreads();

    // Final combine + writeback
    for (int idx = t; idx < NB_UPD*FF; idx += 384) {
        int n = idx >> 7, gg = idx & 127;
        float avv = ash[n*F3 + gg], asv = ash[n*F3 + FF+gg], ass = ash[n*F3 + 2*FF+gg];
        float u0 = Uvs[(n*3+0)*FF+gg], u1 = Uvs[(n*3+1)*FF+gg], u2 = Uvs[(n*3+2)*FF+gg];
        float w0 = Vvs[(n*3+0)*FF+gg], w1v = Vvs[(n*3+1)*FF+gg], w2v = Vvs[(n*3+2)*FF+gg];
        float dot = u0*w0 + u1*w1v + u2*w2v;
        size_t vb = (size_t)(node0+n)*F3;
        g_v[vb + gg]        = sv[(n*3+0)*FF+gg] + avv*u0;
        g_v[vb + FF + gg]   = sv[(n*3+1)*FF+gg] + avv*u1;
        g_v[vb + 2*FF + gg] = sv[(n*3+2)*FF+gg] + avv*u2;
        g_s[(size_t)(node0+n)*FF + gg] = s_in[n*FF + gg] + asv*dot + ass;
    }
}

// ---------------- output head ----------------
__global__ void out_atom_kernel(const float* __restrict__ w1, const float* __restrict__ b1,
                                const float* __restrict__ w2, const float* __restrict__ b2) {
    const int bi = blockIdx.x;
    const int t  = threadIdx.x;                // 128
    __shared__ float ss[FF];
    __shared__ float red[FF];
    ss[t] = g_s[(size_t)bi*FF + t];
    __syncthreads();
    float acc = __ldg(&b1[t]);
    #pragma unroll 8
    for (int k = 0; k < FF; k++) acc = fmaf(ss[k], __ldg(&w1[k*FF + t]), acc);
    float h = silu_f(acc);
    red[t] = h * __ldg(&w2[t]);
    __syncthreads();
    for (int ofs = 64; ofs > 0; ofs >>= 1) {
        if (t < ofs) red[t] += red[t + ofs];
        __syncthreads();
    }
    if (t == 0) g_atom[bi] = red[0] + __ldg(&b2[0]);
}

__global__ void out_reduce_kernel(float* __restrict__ out) {
    const int b = blockIdx.x;
    const int t = threadIdx.x;                 // 64
    __shared__ float r[64];
    r[t] = (t < NAA) ? g_atom[(size_t)b*NAA + t] : 0.0f;
    __syncthreads();
    for (int ofs = 32; ofs > 0; ofs >>= 1) {
        if (t < ofs) r[t] += r[t + ofs];
        __syncthreads();
    }
    if (t == 0) out[b] = r[0];
}

// ---------------- launch ----------------
extern "C" void kernel_launch(void* const* d_in, const int* in_sizes, int n_in,
                              void* d_out, int out_size) {
    const float* pos       = (const float*)d_in[1];
    const int*   node_atom = (const int*)  d_in[3];
    const float* emb       = (const float*)d_in[4];
    const float* msg_w1    = (const float*)d_in[5];
    const float* msg_b1    = (const float*)d_in[6];
    const float* msg_w2    = (const float*)d_in[7];
    const float* msg_b2    = (const float*)d_in[8];
    const float* rbf_w     = (const float*)d_in[9];
    const float* rbf_b     = (const float*)d_in[10];
    const float* upd_U     = (const float*)d_in[11];
    const float* upd_V     = (const float*)d_in[12];
    const float* upd_w1    = (const float*)d_in[13];
    const float* upd_b1    = (const float*)d_in[14];
    const float* upd_w2    = (const float*)d_in[15];
    const float* upd_b2    = (const float*)d_in[16];
    const float* out_w1    = (const float*)d_in[17];
    const float* out_b1    = (const float*)d_in[18];
    const float* out_w2    = (const float*)d_in[19];
    const float* out_b2    = (const float*)d_in[20];

    const int upd_smem = US_TOT * sizeof(float);   // ~94 KB
    cudaFuncSetAttribute(upd_kernel_b, cudaFuncAttributeMaxDynamicSharedMemorySize, upd_smem);

    geom_kernel<<<NN, 64>>>(pos);
    init_kernel<<<NN, FF>>>(emb, node_atom);

    dim3 msg_grid(NN/NB_MSG, 3);
    for (int l = 0; l < LL; l++) {
        phi_kernel_b<<<NN/NB_PHI, 384>>>(msg_w1 + (size_t)l*FF*FF, msg_b1 + (size_t)l*FF,
                                         msg_w2 + (size_t)l*FF*F3, msg_b2 + (size_t)l*F3);
        msg_kernel_c<<<msg_grid, 128>>>(rbf_w + (size_t)l*KK*F3, rbf_b + (size_t)l*F3);
        upd_kernel_b<<<NN/NB_UPD, 384, upd_smem>>>(upd_U + (size_t)l*FF*FF, upd_V + (size_t)l*FF*FF,
                                                   upd_w1 + (size_t)l*2*FF*FF, upd_b1 + (size_t)l*FF,
                                                   upd_w2 + (size_t)l*FF*F3,   upd_b2 + (size_t)l*F3);
    }

    out_atom_kernel<<<NN, FF>>>(out_w1, out_b1, out_w2, out_b2);
    out_reduce_kernel<<<BB, 64>>>((float*)d_out);
}

// round 8
// speedup vs baseline: 3.8326x; 1.2522x over previous
#include <cuda_runtime.h>
#include <math.h>

#define BB   96
#define NAA  48
#define FF   128
#define KK   64
#define LL   6
#define NN   (BB*NAA)          // 4608 nodes
#define F3   (3*FF)            // 384
#define CUTR 5.0f
#define WIN  12                // RBF window width (covers ±5 centers, err < 3e-14)

#define NB_PHI 16
#define NB_MSG 8
#define NB_UPD 8

// upd dynamic smem layout (floats)
#define US_SV   0
#define US_SIN  (US_SV  + NB_UPD*3*FF)
#define US_UV   (US_SIN + NB_UPD*FF)
#define US_VV   (US_UV  + NB_UPD*3*FF)
#define US_VN   (US_VV  + NB_UPD*3*FF)
#define US_HP   (US_VN  + NB_UPD*FF)
#define US_HSH  (US_HP  + 3*NB_UPD*FF)
#define US_ASH  (US_HSH + FF*NB_UPD)
#define US_SVT  (US_ASH + NB_UPD*F3)
#define US_CAT  (US_SVT + F3*NB_UPD)
#define US_TOT  (US_CAT + 2*FF*NB_UPD)     // 23552 floats = 94208 B

// ---------------- device scratch ----------------
__device__ float g_s   [NN*FF];
__device__ float g_v   [NN*F3];
__device__ float g_s2  [NN*FF];
__device__ float g_v2  [NN*F3];
__device__ float g_v2b [NN*F3];
__device__ float g_phi [NN*F3];
__device__ __align__(16) float g_rbfw[NN*NAA*WIN];  // env-premult rbf window
__device__ int   g_kw  [NN*NAA];                    // window start index
__device__ float g_dirc[NN*NAA*3];
__device__ float g_envc[NN*NAA];
__device__ int   g_nbr [NN*NAA];
__device__ int   g_cnt [NN];
__device__ float g_atom[NN];

// ---------------- helpers ----------------
typedef unsigned long long ull;
__device__ __forceinline__ float silu_f(float x) { return x / (1.0f + expf(-x)); }
__device__ __forceinline__ ull pk2(float lo, float hi) {
    ull r; asm("mov.b64 %0, {%1, %2};" : "=l"(r) : "f"(lo), "f"(hi)); return r;
}
__device__ __forceinline__ ull ffma2(ull a, ull b, ull c) {
    ull d; asm("fma.rn.f32x2 %0, %1, %2, %3;" : "=l"(d) : "l"(a), "l"(b), "l"(c)); return d;
}
__device__ __forceinline__ void upk2(ull a, float& lo, float& hi) {
    asm("mov.b64 {%0, %1}, %2;" : "=f"(lo), "=f"(hi) : "l"(a));
}

// ---------------- geometry precompute + neighbor compaction ----------------
__global__ void geom_kernel(const float* __restrict__ pos) {
    const int bi = blockIdx.x;
    const int b  = bi / NAA;
    const int i  = bi % NAA;
    const int t  = threadIdx.x;                // 64

    __shared__ float sd[NAA];
    __shared__ float sdir[NAA][3];
    __shared__ int   smask[NAA];
    __shared__ int   slots[NAA];
    __shared__ int   s_cnt;

    const float* pi = pos + (size_t)(b*NAA + i)*3;
    const float pix = pi[0], piy = pi[1], piz = pi[2];

    if (t < NAA) {
        const float* pj = pos + (size_t)(b*NAA + t)*3;
        float dx = pix - pj[0], dy = piy - pj[1], dz = piz - pj[2];
        float d2 = dx*dx + dy*dy + dz*dz;
        float d  = (t == i) ? 1.0f : sqrtf(d2);
        smask[t] = (t != i) && (d < CUTR);
        sd[t] = d;
        float inv = 1.0f / d;
        sdir[t][0] = dx*inv; sdir[t][1] = dy*inv; sdir[t][2] = dz*inv;
    }
    __syncthreads();
    if (t == 0) {
        int c = 0;
        for (int j = 0; j < NAA; j++) if (smask[j]) slots[c++] = j;
        s_cnt = c;
        g_cnt[bi] = c;
    }
    __syncthreads();
    const int cnt = s_cnt;

    const float GAMMA = (float)(1.0 / ((5.0/64.0)*(5.0/64.0) + 1e-9));
    const float STEP  = (float)(5.0 / 63.0);
    const float PI_F  = 3.14159265358979323846f;

    for (int s = 0; s < cnt; s++) {
        int j = slots[s];
        float d = sd[j];
        float env = 0.5f * (cosf(PI_F * d / CUTR) + 1.0f);
        int ic = __float2int_rn(d / STEP);
        int kw = ic - 5;
        if (kw < 0) kw = 0;
        if (kw > KK - WIN) kw = KK - WIN;
        if (t < WIN) {
            float center = STEP * (float)(kw + t);
            float diff = d - center;
            g_rbfw[((size_t)bi*NAA + s)*WIN + t] = env * expf(-GAMMA * diff * diff);
        } else if (t == WIN) {
            g_kw  [(size_t)bi*NAA + s] = kw;
            g_envc[(size_t)bi*NAA + s] = env;
            g_nbr [(size_t)bi*NAA + s] = b*NAA + j;
            g_dirc[((size_t)bi*NAA + s)*3 + 0] = sdir[j][0];
            g_dirc[((size_t)bi*NAA + s)*3 + 1] = sdir[j][1];
            g_dirc[((size_t)bi*NAA + s)*3 + 2] = sdir[j][2];
        }
    }
}

// ---------------- init ----------------
__global__ void init_kernel(const float* __restrict__ emb,
                            const int*   __restrict__ node_atom) {
    const int bi = blockIdx.x;
    const int t  = threadIdx.x;                // 128
    const int a  = node_atom[bi];
    g_s[(size_t)bi*FF + t] = emb[(size_t)a*FF + t];
    g_v[(size_t)bi*F3 + t]          = 0.0f;
    g_v[(size_t)bi*F3 + FF + t]     = 0.0f;
    g_v[(size_t)bi*F3 + 2*FF + t]   = 0.0f;
}

// ---------------- phi (batched, f32x2 node-pairs) ----------------
__global__ __launch_bounds__(384)
void phi_kernel_b(const float* __restrict__ w1, const float* __restrict__ b1,
                  const float* __restrict__ w2, const float* __restrict__ b2) {
    __shared__ __align__(16) float ss[FF][NB_PHI];
    __shared__ __align__(16) float sh[FF][NB_PHI];
    const int t = threadIdx.x;             // 384
    const int node0 = blockIdx.x * NB_PHI;

    for (int idx = t; idx < NB_PHI*FF; idx += 384) {
        int n = idx >> 7, k = idx & 127;
        ss[k][n] = g_s[(size_t)(node0+n)*FF + k];
    }
    __syncthreads();

    if (t < FF) {
        ull acc2[NB_PHI/2];
        float bb = __ldg(&b1[t]);
        ull bb2 = pk2(bb, bb);
        #pragma unroll
        for (int i = 0; i < NB_PHI/2; i++) acc2[i] = bb2;
        for (int k = 0; k < FF; k++) {
            float w = __ldg(&w1[k*FF + t]);
            ull w2p = pk2(w, w);
            const ulonglong2* sp = (const ulonglong2*)&ss[k][0];
            ulonglong2 q0 = sp[0], q1 = sp[1], q2 = sp[2], q3 = sp[3];
            acc2[0] = ffma2(q0.x, w2p, acc2[0]);
            acc2[1] = ffma2(q0.y, w2p, acc2[1]);
            acc2[2] = ffma2(q1.x, w2p, acc2[2]);
            acc2[3] = ffma2(q1.y, w2p, acc2[3]);
            acc2[4] = ffma2(q2.x, w2p, acc2[4]);
            acc2[5] = ffma2(q2.y, w2p, acc2[5]);
            acc2[6] = ffma2(q3.x, w2p, acc2[6]);
            acc2[7] = ffma2(q3.y, w2p, acc2[7]);
        }
        #pragma unroll
        for (int i = 0; i < NB_PHI/2; i++) {
            float lo, hi; upk2(acc2[i], lo, hi);
            sh[t][2*i]   = silu_f(lo);
            sh[t][2*i+1] = silu_f(hi);
        }
    }
    __syncthreads();

    {
        ull acc2[NB_PHI/2];
        float bb = __ldg(&b2[t]);
        ull bb2 = pk2(bb, bb);
        #pragma unroll
        for (int i = 0; i < NB_PHI/2; i++) acc2[i] = bb2;
        for (int k = 0; k < FF; k++) {
            float w = __ldg(&w2[k*F3 + t]);
            ull w2p = pk2(w, w);
            const ulonglong2* sp = (const ulonglong2*)&sh[k][0];
            ulonglong2 q0 = sp[0], q1 = sp[1], q2 = sp[2], q3 = sp[3];
            acc2[0] = ffma2(q0.x, w2p, acc2[0]);
            acc2[1] = ffma2(q0.y, w2p, acc2[1]);
            acc2[2] = ffma2(q1.x, w2p, acc2[2]);
            acc2[3] = ffma2(q1.y, w2p, acc2[3]);
            acc2[4] = ffma2(q2.x, w2p, acc2[4]);
            acc2[5] = ffma2(q2.y, w2p, acc2[5]);
            acc2[6] = ffma2(q3.x, w2p, acc2[6]);
            acc2[7] = ffma2(q3.y, w2p, acc2[7]);
        }
        #pragma unroll
        for (int i = 0; i < NB_PHI/2; i++) {
            float lo, hi; upk2(acc2[i], lo, hi);
            g_phi[(size_t)(node0+2*i)*F3   + t] = lo;
            g_phi[(size_t)(node0+2*i+1)*F3 + t] = hi;
        }
    }
}

// ---------------- message block: windowed RBF, W in smem ----------------
__global__ __launch_bounds__(128, 6)
void msg_kernel_w(const float* __restrict__ rbf_w, const float* __restrict__ rbf_b) {
    __shared__ float s_w[KK*FF];                    // 32 KB: this chunk's W [k][f]
    __shared__ __align__(16) float s_rbfw[NAA*WIN]; // 2.3 KB
    __shared__ float s_dir[NAA*3];
    __shared__ float s_env[NAA];
    __shared__ int   s_kw [NAA];
    __shared__ int   s_nbr[NAA];

    const int f = threadIdx.x;                 // 128
    const int chunk = blockIdx.y;              // 0..2
    const int t = chunk*FF + f;
    const int node0 = blockIdx.x * NB_MSG;
    const int gbase = (node0 / NAA) * NAA;

    // stage this chunk's W slice [64 k][128 f]
    for (int idx = f; idx < KK*FF; idx += 128) {
        int k = idx >> 7, ff = idx & 127;
        s_w[idx] = __ldg(&rbf_w[k*F3 + chunk*FF + ff]);
    }
    const float bias = __ldg(&rbf_b[t]);
    __syncthreads();

    for (int n = 0; n < NB_MSG; n++) {
        const int bi = node0 + n;
        const int cnt = g_cnt[bi];

        {
            const float4* src4 = (const float4*)(g_rbfw + (size_t)bi*NAA*WIN);
            float4* dst4 = (float4*)s_rbfw;
            for (int idx = f; idx < cnt*3; idx += 128) dst4[idx] = src4[idx];
            if (chunk == 2)
                for (int idx = f; idx < cnt*3; idx += 128)
                    s_dir[idx] = g_dirc[(size_t)bi*NAA*3 + idx];
            for (int idx = f; idx < cnt; idx += 128) {
                s_env[idx] = g_envc[(size_t)bi*NAA + idx];
                s_kw [idx] = g_kw  [(size_t)bi*NAA + idx];
                s_nbr[idx] = g_nbr [(size_t)bi*NAA + idx] - gbase;
            }
        }
        __syncthreads();

        float ac0 = 0.0f, ac1 = 0.0f, ac2 = 0.0f;

        #pragma unroll 2
        for (int s = 0; s < cnt; s++) {
            const float4* rw = (const float4*)(s_rbfw + s*WIN);
            float4 r0 = rw[0], r1 = rw[1], r2 = rw[2];
            const float* wb = s_w + s_kw[s]*FF + f;
            float dA =      r0.x * wb[0*FF];
            float dB =      r0.y * wb[1*FF];
            dA = fmaf(r0.z, wb[2*FF],  dA);
            dB = fmaf(r0.w, wb[3*FF],  dB);
            dA = fmaf(r1.x, wb[4*FF],  dA);
            dB = fmaf(r1.y, wb[5*FF],  dB);
            dA = fmaf(r1.z, wb[6*FF],  dA);
            dB = fmaf(r1.w, wb[7*FF],  dB);
            dA = fmaf(r2.x, wb[8*FF],  dA);
            dB = fmaf(r2.y, wb[9*FF],  dB);
            dA = fmaf(r2.z, wb[10*FF], dA);
            dB = fmaf(r2.w, wb[11*FF], dB);
            float tval = fmaf(s_env[s], bias, dA + dB);

            const int jl = s_nbr[s];
            float x = __ldg(&g_phi[(size_t)(gbase + jl)*F3 + t]) * tval;

            if (chunk == 0) {
                ac0 += x;
            } else if (chunk == 1) {
                const float* vj = g_v + (size_t)(gbase + jl)*F3 + f;
                ac0 = fmaf(x, __ldg(vj),        ac0);
                ac1 = fmaf(x, __ldg(vj + FF),   ac1);
                ac2 = fmaf(x, __ldg(vj + 2*FF), ac2);
            } else {
                ac0 = fmaf(x, s_dir[s*3+0], ac0);
                ac1 = fmaf(x, s_dir[s*3+1], ac1);
                ac2 = fmaf(x, s_dir[s*3+2], ac2);
            }
        }

        if (chunk == 0) {
            g_s2[(size_t)bi*FF + f] = __ldg(&g_s[(size_t)bi*FF + f]) + ac0;
        } else if (chunk == 1) {
            size_t base = (size_t)bi*F3;
            g_v2[base + f]        = __ldg(&g_v[base + f])        + ac0;
            g_v2[base + FF + f]   = __ldg(&g_v[base + FF + f])   + ac1;
            g_v2[base + 2*FF + f] = __ldg(&g_v[base + 2*FF + f]) + ac2;
        } else {
            size_t base = (size_t)bi*F3;
            g_v2b[base + f]        = ac0;
            g_v2b[base + FF + f]   = ac1;
            g_v2b[base + 2*FF + f] = ac2;
        }
        __syncthreads();
    }
}

// ---------------- update block (batched x8, f32x2 node-pairs) ----------------
__global__ __launch_bounds__(384, 2)
void upd_kernel_b(const float* __restrict__ U,  const float* __restrict__ V,
                  const float* __restrict__ w1, const float* __restrict__ b1,
                  const float* __restrict__ w2, const float* __restrict__ b2) {
    extern __shared__ float usm[];
    float* sv   = usm + US_SV;
    float* s_in = usm + US_SIN;
    float* Uvs  = usm + US_UV;
    float* Vvs  = usm + US_VV;
    float* Vn   = usm + US_VN;
    float* hp   = usm + US_HP;
    float* hsh  = usm + US_HSH;
    float* ash  = usm + US_ASH;
    float* sv_t = usm + US_SVT;
    float* cat_t= usm + US_CAT;

    const int t = threadIdx.x;             // 384
    const int node0 = blockIdx.x * NB_UPD;
    const int g = t & 127;
    const int m = t >> 7;                  // 0..2

    for (int idx = t; idx < NB_UPD*F3; idx += 384) {
        float val = g_v2[(size_t)node0*F3 + idx] + g_v2b[(size_t)node0*F3 + idx];
        sv[idx] = val;
        int n = idx / F3, r = idx - n*F3;
        sv_t[r*NB_UPD + n] = val;
    }
    for (int idx = t; idx < NB_UPD*FF; idx += 384)
        s_in[idx] = g_s2[(size_t)node0*FF + idx];
    __syncthreads();

    // Phase A: Uv, Vv  (packed node-pairs)
    {
        ull aU2[NB_UPD/2] = {0,0,0,0}, aV2[NB_UPD/2] = {0,0,0,0};
        for (int k = 0; k < FF; k++) {
            float u  = __ldg(&U[k*FF + g]);
            float vw = __ldg(&V[k*FF + g]);
            ull u2  = pk2(u, u);
            ull vw2 = pk2(vw, vw);
            const ulonglong2* sp = (const ulonglong2*)(sv_t + (m*FF + k)*NB_UPD);
            ulonglong2 q0 = sp[0], q1 = sp[1];
            aU2[0] = ffma2(q0.x, u2,  aU2[0]);
            aU2[1] = ffma2(q0.y, u2,  aU2[1]);
            aU2[2] = ffma2(q1.x, u2,  aU2[2]);
            aU2[3] = ffma2(q1.y, u2,  aU2[3]);
            aV2[0] = ffma2(q0.x, vw2, aV2[0]);
            aV2[1] = ffma2(q0.y, vw2, aV2[1]);
            aV2[2] = ffma2(q1.x, vw2, aV2[2]);
            aV2[3] = ffma2(q1.y, vw2, aV2[3]);
        }
        #pragma unroll
        for (int i = 0; i < NB_UPD/2; i++) {
            float lo, hi;
            upk2(aU2[i], lo, hi);
            Uvs[((2*i)*3 + m)*FF + g]   = lo;
            Uvs[((2*i+1)*3 + m)*FF + g] = hi;
            upk2(aV2[i], lo, hi);
            Vvs[((2*i)*3 + m)*FF + g]   = lo;
            Vvs[((2*i+1)*3 + m)*FF + g] = hi;
        }
    }
    __syncthreads();

    for (int idx = t; idx < NB_UPD*FF; idx += 384) {
        int n = idx >> 7, gg = idx & 127;
        float v0 = Vvs[(n*3+0)*FF+gg], v1 = Vvs[(n*3+1)*FF+gg], v2 = Vvs[(n*3+2)*FF+gg];
        Vn[n*FF + gg] = sqrtf(v0*v0 + v1*v1 + v2*v2 + 1e-8f);
    }
    __syncthreads();

    for (int idx = t; idx < NB_UPD*2*FF; idx += 384) {
        int n = idx >> 8, k = idx & 255;
        float c = (k < FF) ? s_in[n*FF + k] : Vn[n*FF + (k-FF)];
        cat_t[k*NB_UPD + n] = c;
    }
    __syncthreads();

    // Phase B: h partial (k-split across m-groups), packed node-pairs
    {
        int k0 = m*86, k1 = (m == 2) ? 256 : (k0 + 86);
        ull acc2[NB_UPD/2] = {0,0,0,0};
        for (int k = k0; k < k1; k++) {
            float w = __ldg(&w1[k*FF + g]);
            ull w2p = pk2(w, w);
            const ulonglong2* sp = (const ulonglong2*)(cat_t + k*NB_UPD);
            ulonglong2 q0 = sp[0], q1 = sp[1];
            acc2[0] = ffma2(q0.x, w2p, acc2[0]);
            acc2[1] = ffma2(q0.y, w2p, acc2[1]);
            acc2[2] = ffma2(q1.x, w2p, acc2[2]);
            acc2[3] = ffma2(q1.y, w2p, acc2[3]);
        }
        #pragma unroll
        for (int i = 0; i < NB_UPD/2; i++) {
            float lo, hi; upk2(acc2[i], lo, hi);
            hp[(m*NB_UPD + 2*i)*FF + g]   = lo;
            hp[(m*NB_UPD + 2*i+1)*FF + g] = hi;
        }
    }
    __syncthreads();

    for (int idx = t; idx < NB_UPD*FF; idx += 384) {
        int n = idx >> 7, gg = idx & 127;
        float hs = hp[(0*NB_UPD+n)*FF+gg] + hp[(1*NB_UPD+n)*FF+gg] + hp[(2*NB_UPD+n)*FF+gg]
                 + __ldg(&b1[gg]);
        hsh[gg*NB_UPD + n] = silu_f(hs);
    }
    __syncthreads();

    // Phase C: a = h @ w2 + b2, packed node-pairs
    {
        ull acc2[NB_UPD/2];
        float bb = __ldg(&b2[t]);
        ull bb2 = pk2(bb, bb);
        #pragma unroll
        for (int i = 0; i < NB_UPD/2; i++) acc2[i] = bb2;
        for (int k = 0; k < FF; k++) {
            float w = __ldg(&w2[k*F3 + t]);
            ull w2p = pk2(w, w);
            const ulonglong2* sp = (const ulonglong2*)(hsh + k*NB_UPD);
            ulonglong2 q0 = sp[0], q1 = sp[1];
            acc2[0] = ffma2(q0.x, w2p, acc2[0]);
            acc2[1] = ffma2(q0.y, w2p, acc2[1]);
            acc2[2] = ffma2(q1.x, w2p, acc2[2]);
            acc2[3] = ffma2(q1.y, w2p, acc2[3]);
        }
        #pragma unroll
        for (int i = 0; i < NB_UPD/2; i++) {
            float lo, hi; upk2(acc2[i], lo, hi);
            ash[(2*i)*F3 + t]   = lo;
            ash[(2*i+1)*F3 + t] = hi;
        }
    }
    __syncthreads();

    for (int idx = t; idx < NB_UPD*FF; idx += 384) {
        int n = idx >> 7, gg = idx & 127;
        float avv = ash[n*F3 + gg], asv = ash[n*F3 + FF+gg], ass = ash[n*F3 + 2*FF+gg];
        float u0 = Uvs[(n*3+0)*FF+gg], u1 = Uvs[(n*3+1)*FF+gg], u2 = Uvs[(n*3+2)*FF+gg];
        float w0 = Vvs[(n*3+0)*FF+gg], w1v = Vvs[(n*3+1)*FF+gg], w2v = Vvs[(n*3+2)*FF+gg];
        float dot = u0*w0 + u1*w1v + u2*w2v;
        size_t vb = (size_t)(node0+n)*F3;
        g_v[vb + gg]        = sv[(n*3+0)*FF+gg] + avv*u0;
        g_v[vb + FF + gg]   = sv[(n*3+1)*FF+gg] + avv*u1;
        g_v[vb + 2*FF + gg] = sv[(n*3+2)*FF+gg] + avv*u2;
        g_s[(size_t)(node0+n)*FF + gg] = s_in[n*FF + gg] + asv*dot + ass;
    }
}

// ---------------- output head ----------------
__global__ void out_atom_kernel(const float* __restrict__ w1, const float* __restrict__ b1,
                                const float* __restrict__ w2, const float* __restrict__ b2) {
    const int bi = blockIdx.x;
    const int t  = threadIdx.x;                // 128
    __shared__ float ss[FF];
    __shared__ float red[FF];
    ss[t] = g_s[(size_t)bi*FF + t];
    __syncthreads();
    float acc = __ldg(&b1[t]);
    #pragma unroll 8
    for (int k = 0; k < FF; k++) acc = fmaf(ss[k], __ldg(&w1[k*FF + t]), acc);
    float h = silu_f(acc);
    red[t] = h * __ldg(&w2[t]);
    __syncthreads();
    for (int ofs = 64; ofs > 0; ofs >>= 1) {
        if (t < ofs) red[t] += red[t + ofs];
        __syncthreads();
    }
    if (t == 0) g_atom[bi] = red[0] + __ldg(&b2[0]);
}

__global__ void out_reduce_kernel(float* __restrict__ out) {
    const int b = blockIdx.x;
    const int t = threadIdx.x;                 // 64
    __shared__ float r[64];
    r[t] = (t < NAA) ? g_atom[(size_t)b*NAA + t] : 0.0f;
    __syncthreads();
    for (int ofs = 32; ofs > 0; ofs >>= 1) {
        if (t < ofs) r[t] += r[t + ofs];
        __syncthreads();
    }
    if (t == 0) out[b] = r[0];
}

// ---------------- launch ----------------
extern "C" void kernel_launch(void* const* d_in, const int* in_sizes, int n_in,
                              void* d_out, int out_size) {
    const float* pos       = (const float*)d_in[1];
    const int*   node_atom = (const int*)  d_in[3];
    const float* emb       = (const float*)d_in[4];
    const float* msg_w1    = (const float*)d_in[5];
    const float* msg_b1    = (const float*)d_in[6];
    const float* msg_w2    = (const float*)d_in[7];
    const float* msg_b2    = (const float*)d_in[8];
    const float* rbf_w     = (const float*)d_in[9];
    const float* rbf_b     = (const float*)d_in[10];
    const float* upd_U     = (const float*)d_in[11];
    const float* upd_V     = (const float*)d_in[12];
    const float* upd_w1    = (const float*)d_in[13];
    const float* upd_b1    = (const float*)d_in[14];
    const float* upd_w2    = (const float*)d_in[15];
    const float* upd_b2    = (const float*)d_in[16];
    const float* out_w1    = (const float*)d_in[17];
    const float* out_b1    = (const float*)d_in[18];
    const float* out_w2    = (const float*)d_in[19];
    const float* out_b2    = (const float*)d_in[20];

    const int upd_smem = US_TOT * sizeof(float);   // ~94 KB
    cudaFuncSetAttribute(upd_kernel_b, cudaFuncAttributeMaxDynamicSharedMemorySize, upd_smem);

    geom_kernel<<<NN, 64>>>(pos);
    init_kernel<<<NN, FF>>>(emb, node_atom);

    dim3 msg_grid(NN/NB_MSG, 3);
    for (int l = 0; l < LL; l++) {
        phi_kernel_b<<<NN/NB_PHI, 384>>>(msg_w1 + (size_t)l*FF*FF, msg_b1 + (size_t)l*FF,
                                         msg_w2 + (size_t)l*FF*F3, msg_b2 + (size_t)l*F3);
        msg_kernel_w<<<msg_grid, 128>>>(rbf_w + (size_t)l*KK*F3, rbf_b + (size_t)l*F3);
        upd_kernel_b<<<NN/NB_UPD, 384, upd_smem>>>(upd_U + (size_t)l*FF*FF, upd_V + (size_t)l*FF*FF,
                                                   upd_w1 + (size_t)l*2*FF*FF, upd_b1 + (size_t)l*FF,
                                                   upd_w2 + (size_t)l*FF*F3,   upd_b2 + (size_t)l*F3);
    }

    out_atom_kernel<<<NN, FF>>>(out_w1, out_b1, out_w2, out_b2);
    out_reduce_kernel<<<BB, 64>>>((float*)d_out);
}

// round 9
// speedup vs baseline: 3.8381x; 1.0014x over previous
#include <cuda_runtime.h>
#include <math.h>

#define BB   96
#define NAA  48
#define FF   128
#define KK   64
#define LL   6
#define NN   (BB*NAA)          // 4608 nodes
#define F3   (3*FF)            // 384
#define CUTR 5.0f
#define WIN  12                // RBF window width (even-aligned start, covers >= ±5 centers)

#define NB_PHI 16
#define NB_MSG 8
#define NB_UPD 8

// upd dynamic smem layout (floats)
#define US_SV   0
#define US_SIN  (US_SV  + NB_UPD*3*FF)
#define US_UV   (US_SIN + NB_UPD*FF)
#define US_VV   (US_UV  + NB_UPD*3*FF)
#define US_VN   (US_VV  + NB_UPD*3*FF)
#define US_HP   (US_VN  + NB_UPD*FF)
#define US_HSH  (US_HP  + 3*NB_UPD*FF)
#define US_ASH  (US_HSH + FF*NB_UPD)
#define US_SVT  (US_ASH + NB_UPD*F3)
#define US_CAT  (US_SVT + F3*NB_UPD)
#define US_TOT  (US_CAT + 2*FF*NB_UPD)     // 23552 floats = 94208 B

// ---------------- device scratch ----------------
__device__ float g_s   [NN*FF];
__device__ float g_v   [NN*F3];
__device__ float g_s2  [NN*FF];
__device__ float g_v2  [NN*F3];
__device__ float g_v2b [NN*F3];
__device__ float g_phi [NN*F3];
__device__ __align__(16) float g_rbfw[NN*NAA*WIN];  // env-premult rbf window
__device__ int   g_kw  [NN*NAA];                    // window start index (even)
__device__ float g_dirc[NN*NAA*3];
__device__ float g_envc[NN*NAA];
__device__ int   g_nbr [NN*NAA];
__device__ int   g_cnt [NN];
__device__ float g_atom[NN];

// ---------------- helpers ----------------
typedef unsigned long long ull;
__device__ __forceinline__ float silu_f(float x) { return x / (1.0f + expf(-x)); }
__device__ __forceinline__ ull pk2(float lo, float hi) {
    ull r; asm("mov.b64 %0, {%1, %2};" : "=l"(r) : "f"(lo), "f"(hi)); return r;
}
__device__ __forceinline__ ull ffma2(ull a, ull b, ull c) {
    ull d; asm("fma.rn.f32x2 %0, %1, %2, %3;" : "=l"(d) : "l"(a), "l"(b), "l"(c)); return d;
}
__device__ __forceinline__ ull add2(ull a, ull b) {
    ull d; asm("add.rn.f32x2 %0, %1, %2;" : "=l"(d) : "l"(a), "l"(b)); return d;
}
__device__ __forceinline__ void upk2(ull a, float& lo, float& hi) {
    asm("mov.b64 {%0, %1}, %2;" : "=f"(lo), "=f"(hi) : "l"(a));
}

// ---------------- geometry precompute + neighbor compaction ----------------
__global__ void geom_kernel(const float* __restrict__ pos) {
    const int bi = blockIdx.x;
    const int b  = bi / NAA;
    const int i  = bi % NAA;
    const int t  = threadIdx.x;                // 64

    __shared__ float sd[NAA];
    __shared__ float sdir[NAA][3];
    __shared__ int   smask[NAA];
    __shared__ int   slots[NAA];
    __shared__ int   s_cnt;

    const float* pi = pos + (size_t)(b*NAA + i)*3;
    const float pix = pi[0], piy = pi[1], piz = pi[2];

    if (t < NAA) {
        const float* pj = pos + (size_t)(b*NAA + t)*3;
        float dx = pix - pj[0], dy = piy - pj[1], dz = piz - pj[2];
        float d2 = dx*dx + dy*dy + dz*dz;
        float d  = (t == i) ? 1.0f : sqrtf(d2);
        smask[t] = (t != i) && (d < CUTR);
        sd[t] = d;
        float inv = 1.0f / d;
        sdir[t][0] = dx*inv; sdir[t][1] = dy*inv; sdir[t][2] = dz*inv;
    }
    __syncthreads();
    if (t == 0) {
        int c = 0;
        for (int j = 0; j < NAA; j++) if (smask[j]) slots[c++] = j;
        s_cnt = c;
        g_cnt[bi] = c;
    }
    __syncthreads();
    const int cnt = s_cnt;

    const float GAMMA = (float)(1.0 / ((5.0/64.0)*(5.0/64.0) + 1e-9));
    const float STEP  = (float)(5.0 / 63.0);
    const float PI_F  = 3.14159265358979323846f;

    for (int s = 0; s < cnt; s++) {
        int j = slots[s];
        float d = sd[j];
        float env = 0.5f * (cosf(PI_F * d / CUTR) + 1.0f);
        int ic = __float2int_rn(d / STEP);
        int kw = (ic - 5) & ~1;                // even-aligned window start
        if (kw < 0) kw = 0;
        if (kw > KK - WIN) kw = KK - WIN;      // KK-WIN = 52, even
        if (t < WIN) {
            float center = STEP * (float)(kw + t);
            float diff = d - center;
            g_rbfw[((size_t)bi*NAA + s)*WIN + t] = env * expf(-GAMMA * diff * diff);
        } else if (t == WIN) {
            g_kw  [(size_t)bi*NAA + s] = kw;
            g_envc[(size_t)bi*NAA + s] = env;
            g_nbr [(size_t)bi*NAA + s] = b*NAA + j;
            g_dirc[((size_t)bi*NAA + s)*3 + 0] = sdir[j][0];
            g_dirc[((size_t)bi*NAA + s)*3 + 1] = sdir[j][1];
            g_dirc[((size_t)bi*NAA + s)*3 + 2] = sdir[j][2];
        }
    }
}

// ---------------- init ----------------
__global__ void init_kernel(const float* __restrict__ emb,
                            const int*   __restrict__ node_atom) {
    const int bi = blockIdx.x;
    const int t  = threadIdx.x;                // 128
    const int a  = node_atom[bi];
    g_s[(size_t)bi*FF + t] = emb[(size_t)a*FF + t];
    g_v[(size_t)bi*F3 + t]          = 0.0f;
    g_v[(size_t)bi*F3 + FF + t]     = 0.0f;
    g_v[(size_t)bi*F3 + 2*FF + t]   = 0.0f;
}

// ---------------- phi (batched, f32x2 node-pairs) ----------------
__global__ __launch_bounds__(384)
void phi_kernel_b(const float* __restrict__ w1, const float* __restrict__ b1,
                  const float* __restrict__ w2, const float* __restrict__ b2) {
    __shared__ __align__(16) float ss[FF][NB_PHI];
    __shared__ __align__(16) float sh[FF][NB_PHI];
    const int t = threadIdx.x;             // 384
    const int node0 = blockIdx.x * NB_PHI;

    for (int idx = t; idx < NB_PHI*FF; idx += 384) {
        int n = idx >> 7, k = idx & 127;
        ss[k][n] = g_s[(size_t)(node0+n)*FF + k];
    }
    __syncthreads();

    if (t < FF) {
        ull acc2[NB_PHI/2];
        float bb = __ldg(&b1[t]);
        ull bb2 = pk2(bb, bb);
        #pragma unroll
        for (int i = 0; i < NB_PHI/2; i++) acc2[i] = bb2;
        for (int k = 0; k < FF; k++) {
            float w = __ldg(&w1[k*FF + t]);
            ull w2p = pk2(w, w);
            const ulonglong2* sp = (const ulonglong2*)&ss[k][0];
            ulonglong2 q0 = sp[0], q1 = sp[1], q2 = sp[2], q3 = sp[3];
            acc2[0] = ffma2(q0.x, w2p, acc2[0]);
            acc2[1] = ffma2(q0.y, w2p, acc2[1]);
            acc2[2] = ffma2(q1.x, w2p, acc2[2]);
            acc2[3] = ffma2(q1.y, w2p, acc2[3]);
            acc2[4] = ffma2(q2.x, w2p, acc2[4]);
            acc2[5] = ffma2(q2.y, w2p, acc2[5]);
            acc2[6] = ffma2(q3.x, w2p, acc2[6]);
            acc2[7] = ffma2(q3.y, w2p, acc2[7]);
        }
        #pragma unroll
        for (int i = 0; i < NB_PHI/2; i++) {
            float lo, hi; upk2(acc2[i], lo, hi);
            sh[t][2*i]   = silu_f(lo);
            sh[t][2*i+1] = silu_f(hi);
        }
    }
    __syncthreads();

    {
        ull acc2[NB_PHI/2];
        float bb = __ldg(&b2[t]);
        ull bb2 = pk2(bb, bb);
        #pragma unroll
        for (int i = 0; i < NB_PHI/2; i++) acc2[i] = bb2;
        for (int k = 0; k < FF; k++) {
            float w = __ldg(&w2[k*F3 + t]);
            ull w2p = pk2(w, w);
            const ulonglong2* sp = (const ulonglong2*)&sh[k][0];
            ulonglong2 q0 = sp[0], q1 = sp[1], q2 = sp[2], q3 = sp[3];
            acc2[0] = ffma2(q0.x, w2p, acc2[0]);
            acc2[1] = ffma2(q0.y, w2p, acc2[1]);
            acc2[2] = ffma2(q1.x, w2p, acc2[2]);
            acc2[3] = ffma2(q1.y, w2p, acc2[3]);
            acc2[4] = ffma2(q2.x, w2p, acc2[4]);
            acc2[5] = ffma2(q2.y, w2p, acc2[5]);
            acc2[6] = ffma2(q3.x, w2p, acc2[6]);
            acc2[7] = ffma2(q3.y, w2p, acc2[7]);
        }
        #pragma unroll
        for (int i = 0; i < NB_PHI/2; i++) {
            float lo, hi; upk2(acc2[i], lo, hi);
            g_phi[(size_t)(node0+2*i)*F3   + t] = lo;
            g_phi[(size_t)(node0+2*i+1)*F3 + t] = hi;
        }
    }
}

// ---------------- message block: windowed RBF, packed W in smem ----------------
__global__ __launch_bounds__(128, 6)
void msg_kernel_w(const float* __restrict__ rbf_w, const float* __restrict__ rbf_b) {
    __shared__ __align__(16) ull s_wp[(KK/2)*FF];       // 32 KB: packed W pairs [p][f]
    __shared__ __align__(16) float s_rbfw[NAA*WIN];     // 2.3 KB
    __shared__ float s_dir[NAA*3];
    __shared__ float s_env[NAA];
    __shared__ int   s_kw [NAA];
    __shared__ int   s_nbr[NAA];

    const int f = threadIdx.x;                 // 128
    const int chunk = blockIdx.y;              // 0..2
    const int t = chunk*FF + f;
    const int node0 = blockIdx.x * NB_MSG;
    const int gbase = (node0 / NAA) * NAA;

    // stage this chunk's W slice as f32x2 pairs: s_wp[p*FF+f] = (w[2p][f], w[2p+1][f])
    for (int idx = f; idx < (KK/2)*FF; idx += 128) {
        int p = idx >> 7, ff = idx & 127;
        s_wp[idx] = pk2(__ldg(&rbf_w[(2*p)*F3   + chunk*FF + ff]),
                        __ldg(&rbf_w[(2*p+1)*F3 + chunk*FF + ff]));
    }
    const float bias = __ldg(&rbf_b[t]);
    __syncthreads();

    for (int n = 0; n < NB_MSG; n++) {
        const int bi = node0 + n;
        const int cnt = g_cnt[bi];

        {
            const float4* src4 = (const float4*)(g_rbfw + (size_t)bi*NAA*WIN);
            float4* dst4 = (float4*)s_rbfw;
            for (int idx = f; idx < cnt*3; idx += 128) dst4[idx] = src4[idx];
            if (chunk == 2)
                for (int idx = f; idx < cnt*3; idx += 128)
                    s_dir[idx] = g_dirc[(size_t)bi*NAA*3 + idx];
            for (int idx = f; idx < cnt; idx += 128) {
                s_env[idx] = g_envc[(size_t)bi*NAA + idx];
                s_kw [idx] = g_kw  [(size_t)bi*NAA + idx];
                s_nbr[idx] = g_nbr [(size_t)bi*NAA + idx] - gbase;
            }
        }
        __syncthreads();

        float ac0 = 0.0f, ac1 = 0.0f, ac2 = 0.0f;

        #pragma unroll 2
        for (int s = 0; s < cnt; s++) {
            // rbf window as 6 packed pairs (broadcast LDS.128)
            const ulonglong2* rw2 = (const ulonglong2*)(s_rbfw + s*WIN);
            ulonglong2 p01 = rw2[0], p23 = rw2[1], p45 = rw2[2];
            // packed W pairs for this window (6 x LDS.64, stride FF)
            const ull* pw = s_wp + (s_kw[s] >> 1)*FF + f;
            ull a0 = ffma2(p01.x, pw[0*FF], 0ull);
            ull a1 = ffma2(p01.y, pw[1*FF], 0ull);
            a0 = ffma2(p23.x, pw[2*FF], a0);
            a1 = ffma2(p23.y, pw[3*FF], a1);
            a0 = ffma2(p45.x, pw[4*FF], a0);
            a1 = ffma2(p45.y, pw[5*FF], a1);
            ull sa = add2(a0, a1);
            float lo, hi; upk2(sa, lo, hi);
            float tval = fmaf(s_env[s], bias, lo + hi);

            const int jl = s_nbr[s];
            float x = __ldg(&g_phi[(size_t)(gbase + jl)*F3 + t]) * tval;

            if (chunk == 0) {
                ac0 += x;
            } else if (chunk == 1) {
                const float* vj = g_v + (size_t)(gbase + jl)*F3 + f;
                ac0 = fmaf(x, __ldg(vj),        ac0);
                ac1 = fmaf(x, __ldg(vj + FF),   ac1);
                ac2 = fmaf(x, __ldg(vj + 2*FF), ac2);
            } else {
                ac0 = fmaf(x, s_dir[s*3+0], ac0);
                ac1 = fmaf(x, s_dir[s*3+1], ac1);
                ac2 = fmaf(x, s_dir[s*3+2], ac2);
            }
        }

        if (chunk == 0) {
            g_s2[(size_t)bi*FF + f] = __ldg(&g_s[(size_t)bi*FF + f]) + ac0;
        } else if (chunk == 1) {
            size_t base = (size_t)bi*F3;
            g_v2[base + f]        = __ldg(&g_v[base + f])        + ac0;
            g_v2[base + FF + f]   = __ldg(&g_v[base + FF + f])   + ac1;
            g_v2[base + 2*FF + f] = __ldg(&g_v[base + 2*FF + f]) + ac2;
        } else {
            size_t base = (size_t)bi*F3;
            g_v2b[base + f]        = ac0;
            g_v2b[base + FF + f]   = ac1;
            g_v2b[base + 2*FF + f] = ac2;
        }
        __syncthreads();
    }
}

// ---------------- update block (batched x8, f32x2 node-pairs) ----------------
__global__ __launch_bounds__(384, 2)
void upd_kernel_b(const float* __restrict__ U,  const float* __restrict__ V,
                  const float* __restrict__ w1, const float* __restrict__ b1,
                  const float* __restrict__ w2, const float* __restrict__ b2) {
    extern __shared__ float usm[];
    float* sv   = usm + US_SV;
    float* s_in = usm + US_SIN;
    float* Uvs  = usm + US_UV;
    float* Vvs  = usm + US_VV;
    float* Vn   = usm + US_VN;
    float* hp   = usm + US_HP;
    float* hsh  = usm + US_HSH;
    float* ash  = usm + US_ASH;
    float* sv_t = usm + US_SVT;
    float* cat_t= usm + US_CAT;

    const int t = threadIdx.x;             // 384
    const int node0 = blockIdx.x * NB_UPD;
    const int g = t & 127;
    const int m = t >> 7;                  // 0..2

    for (int idx = t; idx < NB_UPD*F3; idx += 384) {
        float val = g_v2[(size_t)node0*F3 + idx] + g_v2b[(size_t)node0*F3 + idx];
        sv[idx] = val;
        int n = idx / F3, r = idx - n*F3;
        sv_t[r*NB_UPD + n] = val;
    }
    for (int idx = t; idx < NB_UPD*FF; idx += 384)
        s_in[idx] = g_s2[(size_t)node0*FF + idx];
    __syncthreads();

    // Phase A: Uv, Vv  (packed node-pairs)
    {
        ull aU2[NB_UPD/2] = {0,0,0,0}, aV2[NB_UPD/2] = {0,0,0,0};
        for (int k = 0; k < FF; k++) {
            float u  = __ldg(&U[k*FF + g]);
            float vw = __ldg(&V[k*FF + g]);
            ull u2  = pk2(u, u);
            ull vw2 = pk2(vw, vw);
            const ulonglong2* sp = (const ulonglong2*)(sv_t + (m*FF + k)*NB_UPD);
            ulonglong2 q0 = sp[0], q1 = sp[1];
            aU2[0] = ffma2(q0.x, u2,  aU2[0]);
            aU2[1] = ffma2(q0.y, u2,  aU2[1]);
            aU2[2] = ffma2(q1.x, u2,  aU2[2]);
            aU2[3] = ffma2(q1.y, u2,  aU2[3]);
            aV2[0] = ffma2(q0.x, vw2, aV2[0]);
            aV2[1] = ffma2(q0.y, vw2, aV2[1]);
            aV2[2] = ffma2(q1.x, vw2, aV2[2]);
            aV2[3] = ffma2(q1.y, vw2, aV2[3]);
        }
        #pragma unroll
        for (int i = 0; i < NB_UPD/2; i++) {
            float lo, hi;
            upk2(aU2[i], lo, hi);
            Uvs[((2*i)*3 + m)*FF + g]   = lo;
            Uvs[((2*i+1)*3 + m)*FF + g] = hi;
            upk2(aV2[i], lo, hi);
            Vvs[((2*i)*3 + m)*FF + g]   = lo;
            Vvs[((2*i+1)*3 + m)*FF + g] = hi;
        }
    }
    __syncthreads();

    for (int idx = t; idx < NB_UPD*FF; idx += 384) {
        int n = idx >> 7, gg = idx & 127;
        float v0 = Vvs[(n*3+0)*FF+gg], v1 = Vvs[(n*3+1)*FF+gg], v2 = Vvs[(n*3+2)*FF+gg];
        Vn[n*FF + gg] = sqrtf(v0*v0 + v1*v1 + v2*v2 + 1e-8f);
    }
    __syncthreads();

    for (int idx = t; idx < NB_UPD*2*FF; idx += 384) {
        int n = idx >> 8, k = idx & 255;
        float c = (k < FF) ? s_in[n*FF + k] : Vn[n*FF + (k-FF)];
        cat_t[k*NB_UPD + n] = c;
    }
    __syncthreads();

    // Phase B: h partial (k-split across m-groups), packed node-pairs
    {
        int k0 = m*86, k1 = (m == 2) ? 256 : (k0 + 86);
        ull acc2[NB_UPD/2] = {0,0,0,0};
        for (int k = k0; k < k1; k++) {
            float w = __ldg(&w1[k*FF + g]);
            ull w2p = pk2(w, w);
            const ulonglong2* sp = (const ulonglong2*)(cat_t + k*NB_UPD);
            ulonglong2 q0 = sp[0], q1 = sp[1];
            acc2[0] = ffma2(q0.x, w2p, acc2[0]);
            acc2[1] = ffma2(q0.y, w2p, acc2[1]);
            acc2[2] = ffma2(q1.x, w2p, acc2[2]);
            acc2[3] = ffma2(q1.y, w2p, acc2[3]);
        }
        #pragma unroll
        for (int i = 0; i < NB_UPD/2; i++) {
            float lo, hi; upk2(acc2[i], lo, hi);
            hp[(m*NB_UPD + 2*i)*FF + g]   = lo;
            hp[(m*NB_UPD + 2*i+1)*FF + g] = hi;
        }
    }
    __syncthreads();

    for (int idx = t; idx < NB_UPD*FF; idx += 384) {
        int n = idx >> 7, gg = idx & 127;
        float hs = hp[(0*NB_UPD+n)*FF+gg] + hp[(1*NB_UPD+n)*FF+gg] + hp[(2*NB_UPD+n)*FF+gg]
                 + __ldg(&b1[gg]);
        hsh[gg*NB_UPD + n] = silu_f(hs);
    }
    __syncthreads();

    // Phase C: a = h @ w2 + b2, packed node-pairs
    {
        ull acc2[NB_UPD/2];
        float bb = __ldg(&b2[t]);
        ull bb2 = pk2(bb, bb);
        #pragma unroll
        for (int i = 0; i < NB_UPD/2; i++) acc2[i] = bb2;
        for (int k = 0; k < FF; k++) {
            float w = __ldg(&w2[k*F3 + t]);
            ull w2p = pk2(w, w);
            const ulonglong2* sp = (const ulonglong2*)(hsh + k*NB_UPD);
            ulonglong2 q0 = sp[0], q1 = sp[1];
            acc2[0] = ffma2(q0.x, w2p, acc2[0]);
            acc2[1] = ffma2(q0.y, w2p, acc2[1]);
            acc2[2] = ffma2(q1.x, w2p, acc2[2]);
            acc2[3] = ffma2(q1.y, w2p, acc2[3]);
        }
        #pragma unroll
        for (int i = 0; i < NB_UPD/2; i++) {
            float lo, hi; upk2(acc2[i], lo, hi);
            ash[(2*i)*F3 + t]   = lo;
            ash[(2*i+1)*F3 + t] = hi;
        }
    }
    __syncthreads();

    for (int idx = t; idx < NB_UPD*FF; idx += 384) {
        int n = idx >> 7, gg = idx & 127;
        float avv = ash[n*F3 + gg], asv = ash[n*F3 + FF+gg], ass = ash[n*F3 + 2*FF+gg];
        float u0 = Uvs[(n*3+0)*FF+gg], u1 = Uvs[(n*3+1)*FF+gg], u2 = Uvs[(n*3+2)*FF+gg];
        float w0 = Vvs[(n*3+0)*FF+gg], w1v = Vvs[(n*3+1)*FF+gg], w2v = Vvs[(n*3+2)*FF+gg];
        float dot = u0*w0 + u1*w1v + u2*w2v;
        size_t vb = (size_t)(node0+n)*F3;
        g_v[vb + gg]        = sv[(n*3+0)*FF+gg] + avv*u0;
        g_v[vb + FF + gg]   = sv[(n*3+1)*FF+gg] + avv*u1;
        g_v[vb + 2*FF + gg] = sv[(n*3+2)*FF+gg] + avv*u2;
        g_s[(size_t)(node0+n)*FF + gg] = s_in[n*FF + gg] + asv*dot + ass;
    }
}

// ---------------- output head ----------------
__global__ void out_atom_kernel(const float* __restrict__ w1, const float* __restrict__ b1,
                                const float* __restrict__ w2, const float* __restrict__ b2) {
    const int bi = blockIdx.x;
    const int t  = threadIdx.x;                // 128
    __shared__ float ss[FF];
    __shared__ float red[FF];
    ss[t] = g_s[(size_t)bi*FF + t];
    __syncthreads();
    float acc = __ldg(&b1[t]);
    #pragma unroll 8
    for (int k = 0; k < FF; k++) acc = fmaf(ss[k], __ldg(&w1[k*FF + t]), acc);
    float h = silu_f(acc);
    red[t] = h * __ldg(&w2[t]);
    __syncthreads();
    for (int ofs = 64; ofs > 0; ofs >>= 1) {
        if (t < ofs) red[t] += red[t + ofs];
        __syncthreads();
    }
    if (t == 0) g_atom[bi] = red[0] + __ldg(&b2[0]);
}

__global__ void out_reduce_kernel(float* __restrict__ out) {
    const int b = blockIdx.x;
    const int t = threadIdx.x;                 // 64
    __shared__ float r[64];
    r[t] = (t < NAA) ? g_atom[(size_t)b*NAA + t] : 0.0f;
    __syncthreads();
    for (int ofs = 32; ofs > 0; ofs >>= 1) {
        if (t < ofs) r[t] += r[t + ofs];
        __syncthreads();
    }
    if (t == 0) out[b] = r[0];
}

// ---------------- launch ----------------
extern "C" void kernel_launch(void* const* d_in, const int* in_sizes, int n_in,
                              void* d_out, int out_size) {
    const float* pos       = (const float*)d_in[1];
    const int*   node_atom = (const int*)  d_in[3];
    const float* emb       = (const float*)d_in[4];
    const float* msg_w1    = (const float*)d_in[5];
    const float* msg_b1    = (const float*)d_in[6];
    const float* msg_w2    = (const float*)d_in[7];
    const float* msg_b2    = (const float*)d_in[8];
    const float* rbf_w     = (const float*)d_in[9];
    const float* rbf_b     = (const float*)d_in[10];
    const float* upd_U     = (const float*)d_in[11];
    const float* upd_V     = (const float*)d_in[12];
    const float* upd_w1    = (const float*)d_in[13];
    const float* upd_b1    = (const float*)d_in[14];
    const float* upd_w2    = (const float*)d_in[15];
    const float* upd_b2    = (const float*)d_in[16];
    const float* out_w1    = (const float*)d_in[17];
    const float* out_b1    = (const float*)d_in[18];
    const float* out_w2    = (const float*)d_in[19];
    const float* out_b2    = (const float*)d_in[20];

    const int upd_smem = US_TOT * sizeof(float);   // ~94 KB
    cudaFuncSetAttribute(upd_kernel_b, cudaFuncAttributeMaxDynamicSharedMemorySize, upd_smem);

    geom_kernel<<<NN, 64>>>(pos);
    init_kernel<<<NN, FF>>>(emb, node_atom);

    dim3 msg_grid(NN/NB_MSG, 3);
    for (int l = 0; l < LL; l++) {
        phi_kernel_b<<<NN/NB_PHI, 384>>>(msg_w1 + (size_t)l*FF*FF, msg_b1 + (size_t)l*FF,
                                         msg_w2 + (size_t)l*FF*F3, msg_b2 + (size_t)l*F3);
        msg_kernel_w<<<msg_grid, 128>>>(rbf_w + (size_t)l*KK*F3, rbf_b + (size_t)l*F3);
        upd_kernel_b<<<NN/NB_UPD, 384, upd_smem>>>(upd_U + (size_t)l*FF*FF, upd_V + (size_t)l*FF*FF,
                                                   upd_w1 + (size_t)l*2*FF*FF, upd_b1 + (size_t)l*FF,
                                                   upd_w2 + (size_t)l*FF*F3,   upd_b2 + (size_t)l*F3);
    }

    out_atom_kernel<<<NN, FF>>>(out_w1, out_b1, out_w2, out_b2);
    out_reduce_kernel<<<BB, 64>>>((float*)d_out);
}

// round 10
// speedup vs baseline: 4.0728x; 1.0612x over previous
#include <cuda_runtime.h>
#include <math.h>

#define BB   96
#define NAA  48
#define FF   128
#define KK   64
#define LL   6
#define NN   (BB*NAA)          // 4608 nodes
#define F3   (3*FF)            // 384
#define CUTR 5.0f
#define WIN  12                // RBF window width (even-aligned start, covers >= ±5 centers)

#define NB_PHI 16
#define NB_MSG 8
#define NB_UPD 8

// upd dynamic smem layout (floats)
#define US_SV   0
#define US_SIN  (US_SV  + NB_UPD*3*FF)
#define US_UV   (US_SIN + NB_UPD*FF)
#define US_VV   (US_UV  + NB_UPD*3*FF)
#define US_VN   (US_VV  + NB_UPD*3*FF)
#define US_HP   (US_VN  + NB_UPD*FF)
#define US_HSH  (US_HP  + 3*NB_UPD*FF)
#define US_ASH  (US_HSH + FF*NB_UPD)
#define US_SVT  (US_ASH + NB_UPD*F3)
#define US_CAT  (US_SVT + F3*NB_UPD)
#define US_TOT  (US_CAT + 2*FF*NB_UPD)     // 23552 floats = 94208 B

// ---------------- device scratch ----------------
__device__ float g_s   [NN*FF];
__device__ float g_v   [NN*F3];
__device__ float g_s2  [NN*FF];
__device__ float g_v2  [NN*F3];
__device__ float g_v2b [NN*F3];
__device__ float g_phi [NN*F3];
__device__ __align__(16) float g_rbfw[NN*NAA*WIN];  // env-premult rbf window
__device__ int   g_kw  [NN*NAA];                    // window start index (even)
__device__ float g_dirc[NN*NAA*3];
__device__ float g_envc[NN*NAA];
__device__ int   g_nbr [NN*NAA];                    // global sender index
__device__ int   g_cnt [NN];
__device__ float g_atom[NN];

// ---------------- helpers ----------------
typedef unsigned long long ull;
__device__ __forceinline__ float silu_f(float x) { return x / (1.0f + expf(-x)); }
__device__ __forceinline__ ull pk2(float lo, float hi) {
    ull r; asm("mov.b64 %0, {%1, %2};" : "=l"(r) : "f"(lo), "f"(hi)); return r;
}
__device__ __forceinline__ ull ffma2(ull a, ull b, ull c) {
    ull d; asm("fma.rn.f32x2 %0, %1, %2, %3;" : "=l"(d) : "l"(a), "l"(b), "l"(c)); return d;
}
__device__ __forceinline__ ull add2(ull a, ull b) {
    ull d; asm("add.rn.f32x2 %0, %1, %2;" : "=l"(d) : "l"(a), "l"(b)); return d;
}
__device__ __forceinline__ void upk2(ull a, float& lo, float& hi) {
    asm("mov.b64 {%0, %1}, %2;" : "=f"(lo), "=f"(hi) : "l"(a));
}
__device__ __forceinline__ unsigned smem_u32(const void* p) {
    return (unsigned)__cvta_generic_to_shared(p);
}
#define CP_A16(dst, src) asm volatile("cp.async.cg.shared.global [%0], [%1], 16;" :: "r"(dst), "l"(src))
#define CP_A4(dst, src)  asm volatile("cp.async.ca.shared.global [%0], [%1], 4;"  :: "r"(dst), "l"(src))
#define CP_COMMIT()      asm volatile("cp.async.commit_group;")
#define CP_WAIT0()       asm volatile("cp.async.wait_group 0;")

// ---------------- geometry precompute + neighbor compaction ----------------
__global__ void geom_kernel(const float* __restrict__ pos) {
    const int bi = blockIdx.x;
    const int b  = bi / NAA;
    const int i  = bi % NAA;
    const int t  = threadIdx.x;                // 64

    __shared__ float sd[NAA];
    __shared__ float sdir[NAA][3];
    __shared__ int   smask[NAA];
    __shared__ int   slots[NAA];
    __shared__ int   s_cnt;

    const float* pi = pos + (size_t)(b*NAA + i)*3;
    const float pix = pi[0], piy = pi[1], piz = pi[2];

    if (t < NAA) {
        const float* pj = pos + (size_t)(b*NAA + t)*3;
        float dx = pix - pj[0], dy = piy - pj[1], dz = piz - pj[2];
        float d2 = dx*dx + dy*dy + dz*dz;
        float d  = (t == i) ? 1.0f : sqrtf(d2);
        smask[t] = (t != i) && (d < CUTR);
        sd[t] = d;
        float inv = 1.0f / d;
        sdir[t][0] = dx*inv; sdir[t][1] = dy*inv; sdir[t][2] = dz*inv;
    }
    __syncthreads();
    if (t == 0) {
        int c = 0;
        for (int j = 0; j < NAA; j++) if (smask[j]) slots[c++] = j;
        s_cnt = c;
        g_cnt[bi] = c;
    }
    __syncthreads();
    const int cnt = s_cnt;

    const float GAMMA = (float)(1.0 / ((5.0/64.0)*(5.0/64.0) + 1e-9));
    const float STEP  = (float)(5.0 / 63.0);
    const float PI_F  = 3.14159265358979323846f;

    for (int s = 0; s < cnt; s++) {
        int j = slots[s];
        float d = sd[j];
        float env = 0.5f * (cosf(PI_F * d / CUTR) + 1.0f);
        int ic = __float2int_rn(d / STEP);
        int kw = (ic - 5) & ~1;                // even-aligned window start
        if (kw < 0) kw = 0;
        if (kw > KK - WIN) kw = KK - WIN;
        if (t < WIN) {
            float center = STEP * (float)(kw + t);
            float diff = d - center;
            g_rbfw[((size_t)bi*NAA + s)*WIN + t] = env * expf(-GAMMA * diff * diff);
        } else if (t == WIN) {
            g_kw  [(size_t)bi*NAA + s] = kw;
            g_envc[(size_t)bi*NAA + s] = env;
            g_nbr [(size_t)bi*NAA + s] = b*NAA + j;
            g_dirc[((size_t)bi*NAA + s)*3 + 0] = sdir[j][0];
            g_dirc[((size_t)bi*NAA + s)*3 + 1] = sdir[j][1];
            g_dirc[((size_t)bi*NAA + s)*3 + 2] = sdir[j][2];
        }
    }
}

// ---------------- init ----------------
__global__ void init_kernel(const float* __restrict__ emb,
                            const int*   __restrict__ node_atom) {
    const int bi = blockIdx.x;
    const int t  = threadIdx.x;                // 128
    const int a  = node_atom[bi];
    g_s[(size_t)bi*FF + t] = emb[(size_t)a*FF + t];
    g_v[(size_t)bi*F3 + t]          = 0.0f;
    g_v[(size_t)bi*F3 + FF + t]     = 0.0f;
    g_v[(size_t)bi*F3 + 2*FF + t]   = 0.0f;
}

// ---------------- phi (batched, f32x2 node-pairs) ----------------
__global__ __launch_bounds__(384)
void phi_kernel_b(const float* __restrict__ w1, const float* __restrict__ b1,
                  const float* __restrict__ w2, const float* __restrict__ b2) {
    __shared__ __align__(16) float ss[FF][NB_PHI];
    __shared__ __align__(16) float sh[FF][NB_PHI];
    const int t = threadIdx.x;             // 384
    const int node0 = blockIdx.x * NB_PHI;

    for (int idx = t; idx < NB_PHI*FF; idx += 384) {
        int n = idx >> 7, k = idx & 127;
        ss[k][n] = g_s[(size_t)(node0+n)*FF + k];
    }
    __syncthreads();

    if (t < FF) {
        ull acc2[NB_PHI/2];
        float bb = __ldg(&b1[t]);
        ull bb2 = pk2(bb, bb);
        #pragma unroll
        for (int i = 0; i < NB_PHI/2; i++) acc2[i] = bb2;
        for (int k = 0; k < FF; k++) {
            float w = __ldg(&w1[k*FF + t]);
            ull w2p = pk2(w, w);
            const ulonglong2* sp = (const ulonglong2*)&ss[k][0];
            ulonglong2 q0 = sp[0], q1 = sp[1], q2 = sp[2], q3 = sp[3];
            acc2[0] = ffma2(q0.x, w2p, acc2[0]);
            acc2[1] = ffma2(q0.y, w2p, acc2[1]);
            acc2[2] = ffma2(q1.x, w2p, acc2[2]);
            acc2[3] = ffma2(q1.y, w2p, acc2[3]);
            acc2[4] = ffma2(q2.x, w2p, acc2[4]);
            acc2[5] = ffma2(q2.y, w2p, acc2[5]);
            acc2[6] = ffma2(q3.x, w2p, acc2[6]);
            acc2[7] = ffma2(q3.y, w2p, acc2[7]);
        }
        #pragma unroll
        for (int i = 0; i < NB_PHI/2; i++) {
            float lo, hi; upk2(acc2[i], lo, hi);
            sh[t][2*i]   = silu_f(lo);
            sh[t][2*i+1] = silu_f(hi);
        }
    }
    __syncthreads();

    {
        ull acc2[NB_PHI/2];
        float bb = __ldg(&b2[t]);
        ull bb2 = pk2(bb, bb);
        #pragma unroll
        for (int i = 0; i < NB_PHI/2; i++) acc2[i] = bb2;
        for (int k = 0; k < FF; k++) {
            float w = __ldg(&w2[k*F3 + t]);
            ull w2p = pk2(w, w);
            const ulonglong2* sp = (const ulonglong2*)&sh[k][0];
            ulonglong2 q0 = sp[0], q1 = sp[1], q2 = sp[2], q3 = sp[3];
            acc2[0] = ffma2(q0.x, w2p, acc2[0]);
            acc2[1] = ffma2(q0.y, w2p, acc2[1]);
            acc2[2] = ffma2(q1.x, w2p, acc2[2]);
            acc2[3] = ffma2(q1.y, w2p, acc2[3]);
            acc2[4] = ffma2(q2.x, w2p, acc2[4]);
            acc2[5] = ffma2(q2.y, w2p, acc2[5]);
            acc2[6] = ffma2(q3.x, w2p, acc2[6]);
            acc2[7] = ffma2(q3.y, w2p, acc2[7]);
        }
        #pragma unroll
        for (int i = 0; i < NB_PHI/2; i++) {
            float lo, hi; upk2(acc2[i], lo, hi);
            g_phi[(size_t)(node0+2*i)*F3   + t] = lo;
            g_phi[(size_t)(node0+2*i+1)*F3 + t] = hi;
        }
    }
}

// ---------------- message block: windowed RBF + cp.async staging + LDG prefetch ----
__global__ __launch_bounds__(128, 5)
void msg_kernel_w(const float* __restrict__ rbf_w, const float* __restrict__ rbf_b) {
    __shared__ __align__(16) ull   s_wp[(KK/2)*FF];     // 32 KB packed W pairs
    __shared__ __align__(16) float s_rbfw[2][NAA*WIN];  // 4.6 KB double-buffered
    __shared__ float s_dir[2][NAA*3];
    __shared__ float s_env[2][NAA];
    __shared__ int   s_kw [2][NAA];
    __shared__ int   s_nbr[2][NAA];

    const int f = threadIdx.x;                 // 128
    const int chunk = blockIdx.y;              // 0..2
    const int t = chunk*FF + f;
    const int node0 = blockIdx.x * NB_MSG;

    // stage this chunk's W slice as f32x2 pairs
    for (int idx = f; idx < (KK/2)*FF; idx += 128) {
        int p = idx >> 7, ff = idx & 127;
        s_wp[idx] = pk2(__ldg(&rbf_w[(2*p)*F3   + chunk*FF + ff]),
                        __ldg(&rbf_w[(2*p+1)*F3 + chunk*FF + ff]));
    }
    const float bias = __ldg(&rbf_b[t]);

    // async-stage node 0 into buffer 0
    {
        const int bi = node0;
        const int c0 = g_cnt[bi];
        const float4* src4 = (const float4*)(g_rbfw + (size_t)bi*NAA*WIN);
        for (int idx = f; idx < c0*3; idx += 128)
            CP_A16(smem_u32(&s_rbfw[0][0]) + idx*16, src4 + idx);
        if (chunk == 2)
            for (int idx = f; idx < c0*3; idx += 128)
                CP_A4(smem_u32(&s_dir[0][0]) + idx*4, g_dirc + (size_t)bi*NAA*3 + idx);
        if (f < c0) {
            CP_A4(smem_u32(&s_env[0][0]) + f*4, g_envc + (size_t)bi*NAA + f);
            CP_A4(smem_u32(&s_kw [0][0]) + f*4, g_kw   + (size_t)bi*NAA + f);
            CP_A4(smem_u32(&s_nbr[0][0]) + f*4, g_nbr  + (size_t)bi*NAA + f);
        }
        CP_COMMIT();
    }
    CP_WAIT0();
    __syncthreads();

    for (int n = 0; n < NB_MSG; n++) {
        const int bi = node0 + n;
        const int cnt = g_cnt[bi];
        const int buf = n & 1;

        // issue async staging for node n+1 into the other buffer
        if (n + 1 < NB_MSG) {
            const int bj = bi + 1;
            const int c1 = g_cnt[bj];
            const int ob = buf ^ 1;
            const float4* src4 = (const float4*)(g_rbfw + (size_t)bj*NAA*WIN);
            for (int idx = f; idx < c1*3; idx += 128)
                CP_A16(smem_u32(&s_rbfw[ob][0]) + idx*16, src4 + idx);
            if (chunk == 2)
                for (int idx = f; idx < c1*3; idx += 128)
                    CP_A4(smem_u32(&s_dir[ob][0]) + idx*4, g_dirc + (size_t)bj*NAA*3 + idx);
            if (f < c1) {
                CP_A4(smem_u32(&s_env[ob][0]) + f*4, g_envc + (size_t)bj*NAA + f);
                CP_A4(smem_u32(&s_kw [ob][0]) + f*4, g_kw   + (size_t)bj*NAA + f);
                CP_A4(smem_u32(&s_nbr[ob][0]) + f*4, g_nbr  + (size_t)bj*NAA + f);
            }
            CP_COMMIT();
        }

        float ac0 = 0.0f, ac1 = 0.0f, ac2 = 0.0f;

        // ---- software-pipelined edge loop (pairs, LDG prefetch depth 1 pair) ----
        float pA = 0.f, pB = 0.f;
        float vA0 = 0.f, vA1 = 0.f, vA2 = 0.f, vB0 = 0.f, vB1 = 0.f, vB2 = 0.f;
        if (cnt > 0) {
            int j0 = s_nbr[buf][0];
            pA = __ldg(&g_phi[(size_t)j0*F3 + t]);
            if (chunk == 1) {
                const float* vj = g_v + (size_t)j0*F3 + f;
                vA0 = __ldg(vj); vA1 = __ldg(vj + FF); vA2 = __ldg(vj + 2*FF);
            }
        }
        if (cnt > 1) {
            int j1 = s_nbr[buf][1];
            pB = __ldg(&g_phi[(size_t)j1*F3 + t]);
            if (chunk == 1) {
                const float* vj = g_v + (size_t)j1*F3 + f;
                vB0 = __ldg(vj); vB1 = __ldg(vj + FF); vB2 = __ldg(vj + 2*FF);
            }
        }

        int s = 0;
        for (; s + 2 <= cnt; s += 2) {
            // prefetch next pair (clamped indices; values unused when OOB)
            float pC, pD, vC0=0.f, vC1=0.f, vC2=0.f, vD0=0.f, vD1=0.f, vD2=0.f;
            {
                int i2 = s + 2 < cnt ? s + 2 : cnt - 1;
                int i3 = s + 3 < cnt ? s + 3 : cnt - 1;
                int j2 = s_nbr[buf][i2], j3 = s_nbr[buf][i3];
                pC = __ldg(&g_phi[(size_t)j2*F3 + t]);
                pD = __ldg(&g_phi[(size_t)j3*F3 + t]);
                if (chunk == 1) {
                    const float* vj2 = g_v + (size_t)j2*F3 + f;
                    const float* vj3 = g_v + (size_t)j3*F3 + f;
                    vC0 = __ldg(vj2); vC1 = __ldg(vj2 + FF); vC2 = __ldg(vj2 + 2*FF);
                    vD0 = __ldg(vj3); vD1 = __ldg(vj3 + FF); vD2 = __ldg(vj3 + 2*FF);
                }
            }

            // dots for edges s, s+1 (two independent chains)
            const ulonglong2* rwA = (const ulonglong2*)(&s_rbfw[buf][0] + s*WIN);
            const ulonglong2* rwB = (const ulonglong2*)(&s_rbfw[buf][0] + (s+1)*WIN);
            ulonglong2 a01 = rwA[0], a23 = rwA[1], a45 = rwA[2];
            ulonglong2 b01 = rwB[0], b23 = rwB[1], b45 = rwB[2];
            const ull* pwA = s_wp + (s_kw[buf][s]   >> 1)*FF + f;
            const ull* pwB = s_wp + (s_kw[buf][s+1] >> 1)*FF + f;
            ull x0 = ffma2(a01.x, pwA[0*FF], 0ull);
            ull x1 = ffma2(a01.y, pwA[1*FF], 0ull);
            ull y0 = ffma2(b01.x, pwB[0*FF], 0ull);
            ull y1 = ffma2(b01.y, pwB[1*FF], 0ull);
            x0 = ffma2(a23.x, pwA[2*FF], x0);
            x1 = ffma2(a23.y, pwA[3*FF], x1);
            y0 = ffma2(b23.x, pwB[2*FF], y0);
            y1 = ffma2(b23.y, pwB[3*FF], y1);
            x0 = ffma2(a45.x, pwA[4*FF], x0);
            x1 = ffma2(a45.y, pwA[5*FF], x1);
            y0 = ffma2(b45.x, pwB[4*FF], y0);
            y1 = ffma2(b45.y, pwB[5*FF], y1);
            ull sa = add2(x0, x1), sb = add2(y0, y1);
            float la, ha, lb, hb;
            upk2(sa, la, ha); upk2(sb, lb, hb);
            float tvalA = fmaf(s_env[buf][s],   bias, la + ha);
            float tvalB = fmaf(s_env[buf][s+1], bias, lb + hb);

            float xA = pA * tvalA;
            float xB = pB * tvalB;

            if (chunk == 0) {
                ac0 += xA + xB;
            } else if (chunk == 1) {
                ac0 = fmaf(xA, vA0, ac0); ac1 = fmaf(xA, vA1, ac1); ac2 = fmaf(xA, vA2, ac2);
                ac0 = fmaf(xB, vB0, ac0); ac1 = fmaf(xB, vB1, ac1); ac2 = fmaf(xB, vB2, ac2);
            } else {
                ac0 = fmaf(xA, s_dir[buf][s*3+0], ac0);
                ac1 = fmaf(xA, s_dir[buf][s*3+1], ac1);
                ac2 = fmaf(xA, s_dir[buf][s*3+2], ac2);
                ac0 = fmaf(xB, s_dir[buf][s*3+3], ac0);
                ac1 = fmaf(xB, s_dir[buf][s*3+4], ac1);
                ac2 = fmaf(xB, s_dir[buf][s*3+5], ac2);
            }

            pA = pC; pB = pD;
            vA0 = vC0; vA1 = vC1; vA2 = vC2;
            vB0 = vD0; vB1 = vD1; vB2 = vD2;
        }
        if (s < cnt) {          // odd tail (uses pA / vA)
            const ulonglong2* rw = (const ulonglong2*)(&s_rbfw[buf][0] + s*WIN);
            ulonglong2 a01 = rw[0], a23 = rw[1], a45 = rw[2];
            const ull* pw = s_wp + (s_kw[buf][s] >> 1)*FF + f;
            ull x0 = ffma2(a01.x, pw[0*FF], 0ull);
            ull x1 = ffma2(a01.y, pw[1*FF], 0ull);
            x0 = ffma2(a23.x, pw[2*FF], x0);
            x1 = ffma2(a23.y, pw[3*FF], x1);
            x0 = ffma2(a45.x, pw[4*FF], x0);
            x1 = ffma2(a45.y, pw[5*FF], x1);
            ull sa = add2(x0, x1);
            float lo, hi; upk2(sa, lo, hi);
            float tval = fmaf(s_env[buf][s], bias, lo + hi);
            float xA = pA * tval;
            if (chunk == 0) {
                ac0 += xA;
            } else if (chunk == 1) {
                ac0 = fmaf(xA, vA0, ac0); ac1 = fmaf(xA, vA1, ac1); ac2 = fmaf(xA, vA2, ac2);
            } else {
                ac0 = fmaf(xA, s_dir[buf][s*3+0], ac0);
                ac1 = fmaf(xA, s_dir[buf][s*3+1], ac1);
                ac2 = fmaf(xA, s_dir[buf][s*3+2], ac2);
            }
        }

        // writeback
        if (chunk == 0) {
            g_s2[(size_t)bi*FF + f] = __ldg(&g_s[(size_t)bi*FF + f]) + ac0;
        } else if (chunk == 1) {
            size_t base = (size_t)bi*F3;
            g_v2[base + f]        = __ldg(&g_v[base + f])        + ac0;
            g_v2[base + FF + f]   = __ldg(&g_v[base + FF + f])   + ac1;
            g_v2[base + 2*FF + f] = __ldg(&g_v[base + 2*FF + f]) + ac2;
        } else {
            size_t base = (size_t)bi*F3;
            g_v2b[base + f]        = ac0;
            g_v2b[base + FF + f]   = ac1;
            g_v2b[base + 2*FF + f] = ac2;
        }

        CP_WAIT0();
        __syncthreads();
    }
}

// ---------------- update block (batched x8, f32x2 node-pairs) ----------------
__global__ __launch_bounds__(384, 2)
void upd_kernel_b(const float* __restrict__ U,  const float* __restrict__ V,
                  const float* __restrict__ w1, const float* __restrict__ b1,
                  const float* __restrict__ w2, const float* __restrict__ b2) {
    extern __shared__ float usm[];
    float* sv   = usm + US_SV;
    float* s_in = usm + US_SIN;
    float* Uvs  = usm + US_UV;
    float* Vvs  = usm + US_VV;
    float* Vn   = usm + US_VN;
    float* hp   = usm + US_HP;
    float* hsh  = usm + US_HSH;
    float* ash  = usm + US_ASH;
    float* sv_t = usm + US_SVT;
    float* cat_t= usm + US_CAT;

    const int t = threadIdx.x;             // 384
    const int node0 = blockIdx.x * NB_UPD;
    const int g = t & 127;
    const int m = t >> 7;                  // 0..2

    for (int idx = t; idx < NB_UPD*F3; idx += 384) {
        float val = g_v2[(size_t)node0*F3 + idx] + g_v2b[(size_t)node0*F3 + idx];
        sv[idx] = val;
        int n = idx / F3, r = idx - n*F3;
        sv_t[r*NB_UPD + n] = val;
    }
    for (int idx = t; idx < NB_UPD*FF; idx += 384)
        s_in[idx] = g_s2[(size_t)node0*FF + idx];
    __syncthreads();

    // Phase A: Uv, Vv  (packed node-pairs)
    {
        ull aU2[NB_UPD/2] = {0,0,0,0}, aV2[NB_UPD/2] = {0,0,0,0};
        for (int k = 0; k < FF; k++) {
            float u  = __ldg(&U[k*FF + g]);
            float vw = __ldg(&V[k*FF + g]);
            ull u2  = pk2(u, u);
            ull vw2 = pk2(vw, vw);
            const ulonglong2* sp = (const ulonglong2*)(sv_t + (m*FF + k)*NB_UPD);
            ulonglong2 q0 = sp[0], q1 = sp[1];
            aU2[0] = ffma2(q0.x, u2,  aU2[0]);
            aU2[1] = ffma2(q0.y, u2,  aU2[1]);
            aU2[2] = ffma2(q1.x, u2,  aU2[2]);
            aU2[3] = ffma2(q1.y, u2,  aU2[3]);
            aV2[0] = ffma2(q0.x, vw2, aV2[0]);
            aV2[1] = ffma2(q0.y, vw2, aV2[1]);
            aV2[2] = ffma2(q1.x, vw2, aV2[2]);
            aV2[3] = ffma2(q1.y, vw2, aV2[3]);
        }
        #pragma unroll
        for (int i = 0; i < NB_UPD/2; i++) {
            float lo, hi;
            upk2(aU2[i], lo, hi);
            Uvs[((2*i)*3 + m)*FF + g]   = lo;
            Uvs[((2*i+1)*3 + m)*FF + g] = hi;
            upk2(aV2[i], lo, hi);
            Vvs[((2*i)*3 + m)*FF + g]   = lo;
            Vvs[((2*i+1)*3 + m)*FF + g] = hi;
        }
    }
    __syncthreads();

    for (int idx = t; idx < NB_UPD*FF; idx += 384) {
        int n = idx >> 7, gg = idx & 127;
        float v0 = Vvs[(n*3+0)*FF+gg], v1 = Vvs[(n*3+1)*FF+gg], v2 = Vvs[(n*3+2)*FF+gg];
        Vn[n*FF + gg] = sqrtf(v0*v0 + v1*v1 + v2*v2 + 1e-8f);
    }
    __syncthreads();

    for (int idx = t; idx < NB_UPD*2*FF; idx += 384) {
        int n = idx >> 8, k = idx & 255;
        float c = (k < FF) ? s_in[n*FF + k] : Vn[n*FF + (k-FF)];
        cat_t[k*NB_UPD + n] = c;
    }
    __syncthreads();

    // Phase B: h partial (k-split across m-groups), packed node-pairs
    {
        int k0 = m*86, k1 = (m == 2) ? 256 : (k0 + 86);
        ull acc2[NB_UPD/2] = {0,0,0,0};
        for (int k = k0; k < k1; k++) {
            float w = __ldg(&w1[k*FF + g]);
            ull w2p = pk2(w, w);
            const ulonglong2* sp = (const ulonglong2*)(cat_t + k*NB_UPD);
            ulonglong2 q0 = sp[0], q1 = sp[1];
            acc2[0] = ffma2(q0.x, w2p, acc2[0]);
            acc2[1] = ffma2(q0.y, w2p, acc2[1]);
            acc2[2] = ffma2(q1.x, w2p, acc2[2]);
            acc2[3] = ffma2(q1.y, w2p, acc2[3]);
        }
        #pragma unroll
        for (int i = 0; i < NB_UPD/2; i++) {
            float lo, hi; upk2(acc2[i], lo, hi);
            hp[(m*NB_UPD + 2*i)*FF + g]   = lo;
            hp[(m*NB_UPD + 2*i+1)*FF + g] = hi;
        }
    }
    __syncthreads();

    for (int idx = t; idx < NB_UPD*FF; idx += 384) {
        int n = idx >> 7, gg = idx & 127;
        float hs = hp[(0*NB_UPD+n)*FF+gg] + hp[(1*NB_UPD+n)*FF+gg] + hp[(2*NB_UPD+n)*FF+gg]
                 + __ldg(&b1[gg]);
        hsh[gg*NB_UPD + n] = silu_f(hs);
    }
    __syncthreads();

    // Phase C: a = h @ w2 + b2, packed node-pairs
    {
        ull acc2[NB_UPD/2];
        float bb = __ldg(&b2[t]);
        ull bb2 = pk2(bb, bb);
        #pragma unroll
        for (int i = 0; i < NB_UPD/2; i++) acc2[i] = bb2;
        for (int k = 0; k < FF; k++) {
            float w = __ldg(&w2[k*F3 + t]);
            ull w2p = pk2(w, w);
            const ulonglong2* sp = (const ulonglong2*)(hsh + k*NB_UPD);
            ulonglong2 q0 = sp[0], q1 = sp[1];
            acc2[0] = ffma2(q0.x, w2p, acc2[0]);
            acc2[1] = ffma2(q0.y, w2p, acc2[1]);
            acc2[2] = ffma2(q1.x, w2p, acc2[2]);
            acc2[3] = ffma2(q1.y, w2p, acc2[3]);
        }
        #pragma unroll
        for (int i = 0; i < NB_UPD/2; i++) {
            float lo, hi; upk2(acc2[i], lo, hi);
            ash[(2*i)*F3 + t]   = lo;
            ash[(2*i+1)*F3 + t] = hi;
        }
    }
    __syncthreads();

    for (int idx = t; idx < NB_UPD*FF; idx += 384) {
        int n = idx >> 7, gg = idx & 127;
        float avv = ash[n*F3 + gg], asv = ash[n*F3 + FF+gg], ass = ash[n*F3 + 2*FF+gg];
        float u0 = Uvs[(n*3+0)*FF+gg], u1 = Uvs[(n*3+1)*FF+gg], u2 = Uvs[(n*3+2)*FF+gg];
        float w0 = Vvs[(n*3+0)*FF+gg], w1v = Vvs[(n*3+1)*FF+gg], w2v = Vvs[(n*3+2)*FF+gg];
        float dot = u0*w0 + u1*w1v + u2*w2v;
        size_t vb = (size_t)(node0+n)*F3;
        g_v[vb + gg]        = sv[(n*3+0)*FF+gg] + avv*u0;
        g_v[vb + FF + gg]   = sv[(n*3+1)*FF+gg] + avv*u1;
        g_v[vb + 2*FF + gg] = sv[(n*3+2)*FF+gg] + avv*u2;
        g_s[(size_t)(node0+n)*FF + gg] = s_in[n*FF + gg] + asv*dot + ass;
    }
}

// ---------------- output head ----------------
__global__ void out_atom_kernel(const float* __restrict__ w1, const float* __restrict__ b1,
                                const float* __restrict__ w2, const float* __restrict__ b2) {
    const int bi = blockIdx.x;
    const int t  = threadIdx.x;                // 128
    __shared__ float ss[FF];
    __shared__ float red[FF];
    ss[t] = g_s[(size_t)bi*FF + t];
    __syncthreads();
    float acc = __ldg(&b1[t]);
    #pragma unroll 8
    for (int k = 0; k < FF; k++) acc = fmaf(ss[k], __ldg(&w1[k*FF + t]), acc);
    float h = silu_f(acc);
    red[t] = h * __ldg(&w2[t]);
    __syncthreads();
    for (int ofs = 64; ofs > 0; ofs >>= 1) {
        if (t < ofs) red[t] += red[t + ofs];
        __syncthreads();
    }
    if (t == 0) g_atom[bi] = red[0] + __ldg(&b2[0]);
}

__global__ void out_reduce_kernel(float* __restrict__ out) {
    const int b = blockIdx.x;
    const int t = threadIdx.x;                 // 64
    __shared__ float r[64];
    r[t] = (t < NAA) ? g_atom[(size_t)b*NAA + t] : 0.0f;
    __syncthreads();
    for (int ofs = 32; ofs > 0; ofs >>= 1) {
        if (t < ofs) r[t] += r[t + ofs];
        __syncthreads();
    }
    if (t == 0) out[b] = r[0];
}

// ---------------- launch ----------------
extern "C" void kernel_launch(void* const* d_in, const int* in_sizes, int n_in,
                              void* d_out, int out_size) {
    const float* pos       = (const float*)d_in[1];
    const int*   node_atom = (const int*)  d_in[3];
    const float* emb       = (const float*)d_in[4];
    const float* msg_w1    = (const float*)d_in[5];
    const float* msg_b1    = (const float*)d_in[6];
    const float* msg_w2    = (const float*)d_in[7];
    const float* msg_b2    = (const float*)d_in[8];
    const float* rbf_w     = (const float*)d_in[9];
    const float* rbf_b     = (const float*)d_in[10];
    const float* upd_U     = (const float*)d_in[11];
    const float* upd_V     = (const float*)d_in[12];
    const float* upd_w1    = (const float*)d_in[13];
    const float* upd_b1    = (const float*)d_in[14];
    const float* upd_w2    = (const float*)d_in[15];
    const float* upd_b2    = (const float*)d_in[16];
    const float* out_w1    = (const float*)d_in[17];
    const float* out_b1    = (const float*)d_in[18];
    const float* out_w2    = (const float*)d_in[19];
    const float* out_b2    = (const float*)d_in[20];

    const int upd_smem = US_TOT * sizeof(float);   // ~94 KB
    cudaFuncSetAttribute(upd_kernel_b, cudaFuncAttributeMaxDynamicSharedMemorySize, upd_smem);

    geom_kernel<<<NN, 64>>>(pos);
    init_kernel<<<NN, FF>>>(emb, node_atom);

    dim3 msg_grid(NN/NB_MSG, 3);
    for (int l = 0; l < LL; l++) {
        phi_kernel_b<<<NN/NB_PHI, 384>>>(msg_w1 + (size_t)l*FF*FF, msg_b1 + (size_t)l*FF,
                                         msg_w2 + (size_t)l*FF*F3, msg_b2 + (size_t)l*F3);
        msg_kernel_w<<<msg_grid, 128>>>(rbf_w + (size_t)l*KK*F3, rbf_b + (size_t)l*F3);
        upd_kernel_b<<<NN/NB_UPD, 384, upd_smem>>>(upd_U + (size_t)l*FF*FF, upd_V + (size_t)l*FF*FF,
                                                   upd_w1 + (size_t)l*2*FF*FF, upd_b1 + (size_t)l*FF,
                                                   upd_w2 + (size_t)l*FF*F3,   upd_b2 + (size_t)l*F3);
    }

    out_atom_kernel<<<NN, FF>>>(out_w1, out_b1, out_w2, out_b2);
    out_reduce_kernel<<<BB, 64>>>((float*)d_out);
}